// round 7
// baseline (speedup 1.0000x reference)
#include <cuda_runtime.h>
#include <math.h>

// Problem dims
#define H_    128
#define B_    16
#define L_    4096
#define SN    64      // SSM state size N
#define CHK   128     // chunk length
#define NCH   32      // chunks (L/CHK)
#define COLS_ 512     // B_*NCH
#define KC_   256     // GEMM-C K dim (2*SN + CHK)
#define SPD   132     // sP stride ([col][k] layout, conflict-free)

// ---------------- device scratch ----------------
static __device__ __align__(16) float g_wC [H_ * 128];         // [h][2n] w^128
static __device__ __align__(16) float g_WAT[H_ * 128 * 128];   // [h][m][j]; m=2n Re, m=2n+1 Im ; tf32
static __device__ __align__(16) float g_QT [H_ * CHK * KC_];   // [h][t][k]; k=2n Re, 2n+1 -Im, k>=128 Toeplitz ; tf32
static __device__ __align__(16) float g_U  [H_ * 128 * COLS_]; // [h][j][col] u, tf32
static __device__ __align__(16) float g_G  [H_ * COLS_ * CHK]; // [h][col][t] tf32
static __device__ double g_part[B_ * 32 * 2];

__device__ __forceinline__ float gelu_f(float v) {
    return 0.5f * v * (1.0f + erff(v * 0.70710678118654752f));
}
__device__ __forceinline__ unsigned f2tf(float f) {
    unsigned u; asm("cvt.rna.tf32.f32 %0, %1;" : "=r"(u) : "f"(f)); return u;
}
__device__ __forceinline__ float tf32f(float f) { return __uint_as_float(f2tf(f)); }

__device__ __forceinline__ void mma8(float* d, const unsigned* a, const unsigned* b) {
    asm volatile("mma.sync.aligned.m16n8k8.row.col.f32.tf32.tf32.f32 "
        "{%0,%1,%2,%3}, {%4,%5,%6,%7}, {%8,%9}, {%0,%1,%2,%3};"
        : "+f"(d[0]), "+f"(d[1]), "+f"(d[2]), "+f"(d[3])
        : "r"(a[0]), "r"(a[1]), "r"(a[2]), "r"(a[3]), "r"(b[0]), "r"(b[1]));
}

// ---------------- precompute: powers + WAT + K + QT ----------------
__global__ __launch_bounds__(256) void k_powQT(
                      const float* __restrict__ Are, const float* __restrict__ Aim,
                      const float* __restrict__ Bre, const float* __restrict__ Bim,
                      const float* __restrict__ Cre, const float* __restrict__ Cim,
                      const float* __restrict__ logdt, const float* __restrict__ Dv) {
    int h = blockIdx.x, tid = threadIdx.x;   // 256 threads
    __shared__ float st[128 * 33];           // power tile [chan][i], chan=2n re / 2n+1 im
    __shared__ float scb[128];
    __shared__ float sKf[128];
    float pre = 0.f, pim = 0.f, wre = 0.f, wim = 0.f, cbre = 0.f, cbim = 0.f;
    if (tid < 64) {
        int n = tid, hn = h * SN + n;
        float dt = expf(logdt[h]);
        float are = Are[hn] * dt, aim = Aim[hn] * dt;
        float mag = expf(are);
        float s, c; sincosf(aim, &s, &c);
        wre = mag * c; wim = mag * s;        // w = exp(dt*A)
        cbre = (Cre[hn] * Bre[hn] - Cim[hn] * Bim[hn]) * dt;
        cbim = (Cre[hn] * Bim[hn] + Cim[hn] * Bre[hn]) * dt;
        scb[2 * n] = cbre; scb[2 * n + 1] = cbim;
        pre = 1.f; pim = 0.f;
    }
    __syncthreads();
    for (int l0 = 0; l0 < 128; l0 += 32) {
        if (tid < 64) {
            int n = tid;
            #pragma unroll 8
            for (int i = 0; i < 32; i++) {
                st[(2 * n) * 33 + i]     = pre;
                st[(2 * n + 1) * 33 + i] = pim;
                float nr = wre * pre - wim * pim;
                pim = wre * pim + wim * pre;
                pre = nr;
            }
        }
        __syncthreads();
        // WAT row m = chan (2n re / 2n+1 im), column 127-l
        for (int idx = tid; idx < 4096; idx += 256) {
            int chan = idx >> 5, i = idx & 31;
            g_WAT[(h * 128 + chan) * 128 + 127 - (l0 + i)] = tf32f(st[chan * 33 + i]);
        }
        if (tid >= 64 && tid < 96) {
            int i = tid - 64;
            float a = 0.f;
            #pragma unroll 8
            for (int n = 0; n < 64; n++)
                a += scb[2 * n] * st[(2 * n) * 33 + i]
                   - scb[2 * n + 1] * st[(2 * n + 1) * 33 + i];
            sKf[l0 + i] = a;
        }
        __syncthreads();
    }
    if (tid < 64) {                          // state now = w^128
        g_wC[h * 128 + 2 * tid]     = pre;
        g_wC[h * 128 + 2 * tid + 1] = pim;
    }
    __syncthreads();
    // QT: k=2n Re(CB*w^(t+1)), k=2n+1 -Im; k>=128 Toeplitz K
    if (tid < 64) {
        int n = tid;
        float qre = cbre * wre - cbim * wim; // CB * w^1
        float qim = cbre * wim + cbim * wre;
        for (int t = 0; t < CHK; t++) {
            *(float2*)&g_QT[(h * CHK + t) * KC_ + 2 * n] =
                make_float2(tf32f(qre), tf32f(-qim));
            float nr = qre * wre - qim * wim;
            qim = qre * wim + qim * wre;
            qre = nr;
        }
    } else if (tid < 192) {
        int j = tid - 64;                    // 0..127
        float K0D = sKf[0] + Dv[h];
        for (int t = 0; t < CHK; t++) {
            float v = (j < t) ? sKf[t - j] : (j == t ? K0D : 0.f);
            g_QT[(h * CHK + t) * KC_ + 128 + j] = tf32f(v);
        }
    }
}

// ---------------- LayerNorm partial sums over (L,H) per batch ----------------
__global__ __launch_bounds__(256) void k_lnpart(const float* __restrict__ x) {
    int b = blockIdx.x, s = blockIdx.y;      // 16 x 32
    const float4* p = (const float4*)(x + (size_t)b * (L_ * H_)) + (size_t)s * 4096;
    float su = 0.f, sq = 0.f;
    for (int i = threadIdx.x; i < 4096; i += 256) {
        float4 v = p[i];
        su += v.x + v.y + v.z + v.w;
        sq += v.x * v.x + v.y * v.y + v.z * v.z + v.w * v.w;
    }
    double ds = (double)su, dq = (double)sq;
    #pragma unroll
    for (int o = 16; o > 0; o >>= 1) {
        ds += __shfl_down_sync(0xffffffffu, ds, o);
        dq += __shfl_down_sync(0xffffffffu, dq, o);
    }
    __shared__ double ws[8], wq[8];
    int lane = threadIdx.x & 31, warp = threadIdx.x >> 5;
    if (lane == 0) { ws[warp] = ds; wq[warp] = dq; }
    __syncthreads();
    if (threadIdx.x == 0) {
        double S = 0, Q = 0;
        for (int i = 0; i < 8; i++) { S += ws[i]; Q += wq[i]; }
        g_part[(b * 32 + s) * 2]     = S;
        g_part[(b * 32 + s) * 2 + 1] = Q;
    }
}

// ---------------- normalize + transpose into g_U (tf32); LN-final folded in ----------------
__global__ __launch_bounds__(128) void k_xpose(const float* __restrict__ x) {
    int b = blockIdx.x, j = blockIdx.y;
    int tid = threadIdx.x;                   // 128
    __shared__ float sx[32 * 129];
    __shared__ float sms[2];
    if (tid < 32) {
        double s = g_part[(b * 32 + tid) * 2];
        double q = g_part[(b * 32 + tid) * 2 + 1];
        #pragma unroll
        for (int o = 16; o > 0; o >>= 1) {
            s += __shfl_down_sync(0xffffffffu, s, o);
            q += __shfl_down_sync(0xffffffffu, q, o);
        }
        if (tid == 0) {
            double inv = 1.0 / (double)(L_ * H_);
            double mean = s * inv;
            double var  = q * inv - mean * mean;
            sms[0] = (float)mean;
            sms[1] = (float)(1.0 / sqrt(var + 1e-5));
        }
    }
    #pragma unroll 4
    for (int c = 0; c < 32; c++)
        sx[c * 129 + tid] = x[((size_t)b * L_ + (size_t)c * 128 + j) * H_ + tid];
    __syncthreads();
    float mean = sms[0], rstd = sms[1];
    int w = tid >> 5, lane = tid & 31;
    for (int h0 = w; h0 < 128; h0 += 4)
        g_U[(h0 * 128 + j) * COLS_ + b * 32 + lane] =
            tf32f((sx[lane * 129 + h0] - mean) * rstd);
}

// ---------------- tf32 GEMM compute panel (A,B smem, [row*36+k] layout) ----------------
#define GEMM_COMPUTE_PANEL(As, Bs, acc, wm, wn, g, tg)                         \
    _Pragma("unroll")                                                          \
    for (int ks = 0; ks < 32; ks += 8) {                                       \
        unsigned a[4][4], bf[4][2];                                            \
        _Pragma("unroll")                                                      \
        for (int mt = 0; mt < 4; mt++) {                                       \
            int r = (wm) * 64 + mt * 16 + (g);                                 \
            a[mt][0] = (As)[r * 36 + ks + (tg)];                               \
            a[mt][1] = (As)[(r + 8) * 36 + ks + (tg)];                         \
            a[mt][2] = (As)[r * 36 + ks + (tg) + 4];                           \
            a[mt][3] = (As)[(r + 8) * 36 + ks + (tg) + 4];                     \
        }                                                                      \
        _Pragma("unroll")                                                      \
        for (int nt = 0; nt < 4; nt++) {                                       \
            int nn = (wn) * 32 + nt * 8 + (g);                                 \
            bf[nt][0] = (Bs)[nn * 36 + ks + (tg)];                             \
            bf[nt][1] = (Bs)[nn * 36 + ks + (tg) + 4];                         \
        }                                                                      \
        _Pragma("unroll")                                                      \
        for (int mt = 0; mt < 4; mt++)                                         \
            _Pragma("unroll")                                                  \
            for (int nt = 0; nt < 4; nt++)                                     \
                mma8(acc[mt][nt], a[mt], bf[nt]);                              \
    }

// A from sP ([col*SPD + k] layout, tf32-prerounded floats), global k offset ko
#define GEMM_PANEL_SP(ko, Bs, acc, wm, wn, g, tg)                              \
    _Pragma("unroll")                                                          \
    for (int ks = 0; ks < 32; ks += 8) {                                       \
        unsigned a[4][4], bf[4][2];                                            \
        _Pragma("unroll")                                                      \
        for (int mt = 0; mt < 4; mt++) {                                       \
            int r = (wm) * 64 + mt * 16 + (g);                                 \
            a[mt][0] = __float_as_uint(sP[r * SPD + (ko) + ks + (tg)]);        \
            a[mt][1] = __float_as_uint(sP[(r + 8) * SPD + (ko) + ks + (tg)]);  \
            a[mt][2] = __float_as_uint(sP[r * SPD + (ko) + ks + (tg) + 4]);    \
            a[mt][3] = __float_as_uint(sP[(r + 8) * SPD + (ko) + ks + (tg) + 4]);\
        }                                                                      \
        _Pragma("unroll")                                                      \
        for (int nt = 0; nt < 4; nt++) {                                       \
            int nn = (wn) * 32 + nt * 8 + (g);                                 \
            bf[nt][0] = (Bs)[nn * 36 + ks + (tg)];                             \
            bf[nt][1] = (Bs)[nn * 36 + ks + (tg) + 4];                         \
        }                                                                      \
        _Pragma("unroll")                                                      \
        for (int mt = 0; mt < 4; mt++)                                         \
            _Pragma("unroll")                                                  \
            for (int nt = 0; nt < 4; nt++)                                     \
                mma8(acc[mt][nt], a[mt], bf[nt]);                              \
    }

// ---------------- fused GEMM-A + prefix scan + GEMM-C (2 CTAs/SM) ----------------
#define SMEM_ABC ((2 * 4608) * 4 + 128 * SPD * 4)
__global__ __launch_bounds__(256, 2) void k_gemmABC() {
    extern __shared__ unsigned smem[];
    unsigned* Abuf = smem;                       // [4608]
    unsigned* Bbuf = smem + 4608;                // [4608]
    float* sP = (float*)(smem + 2 * 4608);       // [128*SPD]: Sin as [col][k]
    int h = blockIdx.x >> 2, col0 = (blockIdx.x & 3) * 128;
    int tid = threadIdx.x, lane = tid & 31, warp = tid >> 5;
    int wm = warp & 1, wn = warp >> 1, g = lane >> 2, tg = lane & 3;
    const float* srcU = &g_U[h * 128 * COLS_];
    const float* srcW = &g_WAT[h * 128 * 128];
    const float* srcQ = &g_QT[h * CHK * KC_];

    uint4 raA[4], raB[4];
    // reg-prefetch loads
    #define LOADW(p) { _Pragma("unroll") for (int i = 0; i < 4; i++) {         \
        int idx = tid + i * 256; int m = idx >> 3, k4 = (idx & 7) * 4;         \
        raA[i] = *(const uint4*)&srcW[m * 128 + (p) * 32 + k4]; } }
    #define LOADU(p, dst) { _Pragma("unroll") for (int i = 0; i < 4; i++) {    \
        int idx = tid + i * 256; int kk = idx >> 5, c = (idx & 31) * 4;        \
        dst[i] = *(const uint4*)&srcU[((p) * 32 + kk) * COLS_ + col0 + c]; } }
    #define LOADQ(p) { _Pragma("unroll") for (int i = 0; i < 4; i++) {         \
        int idx = tid + i * 256; int t = idx >> 3, k4 = (idx & 7) * 4;         \
        raB[i] = *(const uint4*)&srcQ[t * KC_ + (p) * 32 + k4]; } }
    // smem stores
    #define STS_DIRECT(buf, src) { _Pragma("unroll") for (int i = 0; i < 4; i++) { \
        int idx = tid + i * 256; int m = idx >> 3, k4 = (idx & 7) * 4;         \
        *(uint4*)&(buf)[m * 36 + k4] = src[i]; } }
    #define STS_XPOSE(buf, src) { _Pragma("unroll") for (int i = 0; i < 4; i++) { \
        int idx = tid + i * 256; int kk = idx >> 5, c = (idx & 31) * 4;        \
        (buf)[c * 36 + kk] = src[i].x; (buf)[(c + 1) * 36 + kk] = src[i].y;    \
        (buf)[(c + 2) * 36 + kk] = src[i].z; (buf)[(c + 3) * 36 + kk] = src[i].w; } }

    LOADW(0); LOADU(0, raB);
    float acc[4][4][4] = {};
    // ---- phase 1: P[m][col] = sum_j WAT[m][j]*u[j][col] ----
    for (int p = 0; p < 4; p++) {
        STS_DIRECT(Abuf, raA);
        STS_XPOSE(Bbuf, raB);
        __syncthreads();
        if (p < 3) { LOADW(p + 1); LOADU(p + 1, raB); }
        else       { LOADQ(0); }             // prefetch QT panel 0 for phase 2
        GEMM_COMPUTE_PANEL(Abuf, Bbuf, acc, wm, wn, g, tg);
        __syncthreads();
    }
    // ---- stage P into sP[col][m] (transposed) ----
    #pragma unroll
    for (int mt = 0; mt < 4; mt++)
        #pragma unroll
        for (int nt = 0; nt < 4; nt++) {
            int r0 = wm * 64 + mt * 16 + g;          // m (state row)
            int cl = wn * 32 + nt * 8 + 2 * tg;      // col
            sP[cl * SPD + r0]           = acc[mt][nt][0];
            sP[(cl + 1) * SPD + r0]     = acc[mt][nt][1];
            sP[cl * SPD + r0 + 8]       = acc[mt][nt][2];
            sP[(cl + 1) * SPD + r0 + 8] = acc[mt][nt][3];
        }
    __syncthreads();
    // ---- prefix scan over 32 chunks; states interleaved at k=2n,2n+1 ----
    {
        int n = tid & 63, bl = tid >> 6;
        float wre = g_wC[h * 128 + 2 * n], wim = g_wC[h * 128 + 2 * n + 1];
        float sre = 0.f, sim = 0.f;
        #pragma unroll 4
        for (int c = 0; c < 32; c++) {
            int colI = bl * 32 + c;
            float2 pv = *(float2*)&sP[colI * SPD + 2 * n];
            *(float2*)&sP[colI * SPD + 2 * n] = make_float2(tf32f(sre), tf32f(sim));
            float nr = wre * sre - wim * sim + pv.x;
            sim = wre * sim + wim * sre + pv.y;
            sre = nr;
        }
    }
    __syncthreads();
    // ---- phase 2: G[col][t] = gelu( sum_k [Sin;u](k,col) * QT[t][k] ) ----
    #pragma unroll
    for (int mt = 0; mt < 4; mt++)
        #pragma unroll
        for (int nt = 0; nt < 4; nt++)
            #pragma unroll
            for (int q = 0; q < 4; q++) acc[mt][nt][q] = 0.f;
    for (int p = 0; p < 8; p++) {
        STS_DIRECT(Bbuf, raB);                       // QT panel p
        if (p >= 4) STS_XPOSE(Abuf, raA);            // u panel p-4
        __syncthreads();
        if (p < 7) {
            LOADQ(p + 1);
            if (p + 1 >= 4) LOADU(p + 1 - 4, raA);
        }
        if (p < 4) { GEMM_PANEL_SP(p * 32, Bbuf, acc, wm, wn, g, tg); }
        else       { GEMM_COMPUTE_PANEL(Abuf, Bbuf, acc, wm, wn, g, tg); }
        __syncthreads();
    }
    // ---- epilogue: GELU, write G[h][col][t] ----
    float* Gd = &g_G[h * COLS_ * CHK];
    #pragma unroll
    for (int mt = 0; mt < 4; mt++)
        #pragma unroll
        for (int nt = 0; nt < 4; nt++) {
            int r0 = col0 + wm * 64 + mt * 16 + g;   // col
            int c = wn * 32 + nt * 8 + 2 * tg;       // t
            *(float2*)&Gd[r0 * CHK + c] =
                make_float2(tf32f(gelu_f(acc[mt][nt][0])), tf32f(gelu_f(acc[mt][nt][1])));
            *(float2*)&Gd[(r0 + 8) * CHK + c] =
                make_float2(tf32f(gelu_f(acc[mt][nt][2])), tf32f(gelu_f(acc[mt][nt][3])));
        }
    #undef LOADW
    #undef LOADU
    #undef LOADQ
    #undef STS_DIRECT
    #undef STS_XPOSE
}

// ---------------- GEMM-D: out[t][o] = sum_h G[h][col][t] * W1[o][h] + b1 + x ----------------
__global__ __launch_bounds__(256) void k_gemmD(const float* __restrict__ x,
                                               const float* __restrict__ W1,
                                               const float* __restrict__ b1,
                                               float* __restrict__ out) {
    __shared__ unsigned As[128 * 36], Bs[128 * 36];
    int col = blockIdx.x;                    // (b,c)
    int b = col >> 5, c = col & 31;
    int tid = threadIdx.x, lane = tid & 31, warp = tid >> 5;
    int wm = warp & 1, wn = warp >> 1, g = lane >> 2, tg = lane & 3;
    float acc[4][4][4] = {};
    uint4 ra[4], rb[4];

    #define GD_LOAD(h0) {                                                      \
        _Pragma("unroll") for (int i = 0; i < 4; i++) {                        \
            int idx = tid + i * 256; int kk = idx >> 5, t4 = (idx & 31) * 4;   \
            ra[i] = *(const uint4*)&g_G[(((h0) + kk) * COLS_ + col) * CHK + t4]; } \
        _Pragma("unroll") for (int i = 0; i < 4; i++) {                        \
            int idx = tid + i * 256; int o = idx >> 3, k4 = (idx & 7) * 4;     \
            float4 v = *(const float4*)&W1[o * H_ + (h0) + k4];                \
            rb[i].x = f2tf(v.x); rb[i].y = f2tf(v.y);                          \
            rb[i].z = f2tf(v.z); rb[i].w = f2tf(v.w); } }
    #define GD_STORE() {                                                       \
        _Pragma("unroll") for (int i = 0; i < 4; i++) {                        \
            int idx = tid + i * 256; int kk = idx >> 5, t4 = (idx & 31) * 4;   \
            As[t4 * 36 + kk] = ra[i].x; As[(t4 + 1) * 36 + kk] = ra[i].y;      \
            As[(t4 + 2) * 36 + kk] = ra[i].z; As[(t4 + 3) * 36 + kk] = ra[i].w; } \
        _Pragma("unroll") for (int i = 0; i < 4; i++) {                        \
            int idx = tid + i * 256; int o = idx >> 3, k4 = (idx & 7) * 4;     \
            *(uint4*)&Bs[o * 36 + k4] = rb[i]; } }

    GD_LOAD(0); GD_STORE(); __syncthreads();
    for (int h0 = 0; h0 < 128; h0 += 32) {
        bool more = (h0 + 32) < 128;
        if (more) GD_LOAD(h0 + 32);
        GEMM_COMPUTE_PANEL(As, Bs, acc, wm, wn, g, tg);
        __syncthreads();
        if (more) { GD_STORE(); __syncthreads(); }
    }
    #pragma unroll
    for (int mt = 0; mt < 4; mt++)
        #pragma unroll
        for (int nt = 0; nt < 4; nt++) {
            int t0 = wm * 64 + mt * 16 + g;
            int o  = wn * 32 + nt * 8 + 2 * tg;
            float2 bias = *(const float2*)&b1[o];
            size_t base0 = ((size_t)b * L_ + c * 128 + t0) * H_ + o;
            size_t base1 = ((size_t)b * L_ + c * 128 + t0 + 8) * H_ + o;
            float2 x0 = *(const float2*)&x[base0];
            float2 x1 = *(const float2*)&x[base1];
            *(float2*)&out[base0] = make_float2(acc[mt][nt][0] + bias.x + x0.x,
                                                acc[mt][nt][1] + bias.y + x0.y);
            *(float2*)&out[base1] = make_float2(acc[mt][nt][2] + bias.x + x1.x,
                                                acc[mt][nt][3] + bias.y + x1.y);
        }
    #undef GD_LOAD
    #undef GD_STORE
}

// ---------------- launch ----------------
extern "C" void kernel_launch(void* const* d_in, const int* in_sizes, int n_in,
                              void* d_out, int out_size) {
    const float* x     = (const float*)d_in[0];
    const float* Are   = (const float*)d_in[1];
    const float* Aim   = (const float*)d_in[2];
    const float* Bre   = (const float*)d_in[3];
    const float* Bim   = (const float*)d_in[4];
    const float* Cre   = (const float*)d_in[5];
    const float* Cim   = (const float*)d_in[6];
    const float* Dv    = (const float*)d_in[7];
    const float* logdt = (const float*)d_in[8];
    const float* W1    = (const float*)d_in[9];
    const float* b1    = (const float*)d_in[10];
    float* out = (float*)d_out;

    cudaFuncSetAttribute(k_gemmABC, cudaFuncAttributeMaxDynamicSharedMemorySize, SMEM_ABC);

    k_powQT<<<H_, 256>>>(Are, Aim, Bre, Bim, Cre, Cim, logdt, Dv);
    k_lnpart<<<dim3(B_, 32), 256>>>(x);
    k_xpose<<<dim3(B_, CHK), 128>>>(x);
    k_gemmABC<<<H_ * 4, 256, SMEM_ABC>>>();
    k_gemmD<<<COLS_, 256>>>(x, W1, b1, out);
}

// round 9
// speedup vs baseline: 1.0213x; 1.0213x over previous
#include <cuda_runtime.h>
#include <math.h>

// Problem dims
#define H_    128
#define B_    16
#define L_    4096
#define SN    64      // SSM state size N
#define CHK   128     // chunk length
#define NCH   32      // chunks (L/CHK)
#define COLS_ 512     // B_*NCH
#define KC_   256     // GEMM-C K dim (2*SN + CHK)
#define SPD   132     // sP stride ([col][k] layout, conflict-free)

// ---------------- device scratch ----------------
static __device__ __align__(16) float g_wC [H_ * 128];         // [h][2n] w^128
static __device__ __align__(16) float g_WAT[H_ * 128 * 128];   // [h][m][j'] k-permuted, tf32
static __device__ __align__(16) float g_QT [H_ * CHK * KC_];   // [h][t][k'] k-permuted, tf32
static __device__ __align__(16) float g_U  [H_ * 128 * COLS_]; // [h][j][col] u, tf32 (natural)
static __device__ __align__(16) float g_G  [H_ * COLS_ * CHK]; // [h][col][t] tf32 (natural)
static __device__ double g_part[B_ * 32 * 2];

__device__ __forceinline__ float gelu_f(float v) {
    return 0.5f * v * (1.0f + erff(v * 0.70710678118654752f));
}
__device__ __forceinline__ unsigned f2tf(float f) {
    unsigned u; asm("cvt.rna.tf32.f32 %0, %1;" : "=r"(u) : "f"(f)); return u;
}
__device__ __forceinline__ float tf32f(float f) { return __uint_as_float(f2tf(f)); }
// within-8 k permutation: [k0,k4,k1,k5,k2,k6,k3,k7]
__device__ __forceinline__ int perm8(int j) { return ((j & 3) << 1) | ((j >> 2) & 1); }
__device__ __forceinline__ int kperm(int k) { return (k & ~7) | perm8(k & 7); }

__device__ __forceinline__ void mma8(float* d, const unsigned* a, const unsigned* b) {
    asm volatile("mma.sync.aligned.m16n8k8.row.col.f32.tf32.tf32.f32 "
        "{%0,%1,%2,%3}, {%4,%5,%6,%7}, {%8,%9}, {%0,%1,%2,%3};"
        : "+f"(d[0]), "+f"(d[1]), "+f"(d[2]), "+f"(d[3])
        : "r"(a[0]), "r"(a[1]), "r"(a[2]), "r"(a[3]), "r"(b[0]), "r"(b[1]));
}

// ---------------- precompute: powers + WAT + K + QT (k-permuted outputs) ----------------
__global__ __launch_bounds__(256) void k_powQT(
                      const float* __restrict__ Are, const float* __restrict__ Aim,
                      const float* __restrict__ Bre, const float* __restrict__ Bim,
                      const float* __restrict__ Cre, const float* __restrict__ Cim,
                      const float* __restrict__ logdt, const float* __restrict__ Dv) {
    int h = blockIdx.x, tid = threadIdx.x;   // 256 threads
    __shared__ float st[128 * 33];           // power tile [chan][i]
    __shared__ float scb[128];
    __shared__ float sKf[128];
    float pre = 0.f, pim = 0.f, wre = 0.f, wim = 0.f, cbre = 0.f, cbim = 0.f;
    if (tid < 64) {
        int n = tid, hn = h * SN + n;
        float dt = expf(logdt[h]);
        float are = Are[hn] * dt, aim = Aim[hn] * dt;
        float mag = expf(are);
        float s, c; sincosf(aim, &s, &c);
        wre = mag * c; wim = mag * s;        // w = exp(dt*A)
        cbre = (Cre[hn] * Bre[hn] - Cim[hn] * Bim[hn]) * dt;
        cbim = (Cre[hn] * Bim[hn] + Cim[hn] * Bre[hn]) * dt;
        scb[2 * n] = cbre; scb[2 * n + 1] = cbim;
        pre = 1.f; pim = 0.f;
    }
    __syncthreads();
    for (int l0 = 0; l0 < 128; l0 += 32) {
        if (tid < 64) {
            int n = tid;
            #pragma unroll 8
            for (int i = 0; i < 32; i++) {
                st[(2 * n) * 33 + i]     = pre;
                st[(2 * n + 1) * 33 + i] = pim;
                float nr = wre * pre - wim * pim;
                pim = wre * pim + wim * pre;
                pre = nr;
            }
        }
        __syncthreads();
        // WAT row m = chan (2n re / 2n+1 im), column kperm(127-l)
        for (int idx = tid; idx < 4096; idx += 256) {
            int chan = idx >> 5, i = idx & 31;
            g_WAT[(h * 128 + chan) * 128 + kperm(127 - (l0 + i))] = tf32f(st[chan * 33 + i]);
        }
        if (tid >= 64 && tid < 96) {
            int i = tid - 64;
            float a = 0.f;
            #pragma unroll 8
            for (int n = 0; n < 64; n++)
                a += scb[2 * n] * st[(2 * n) * 33 + i]
                   - scb[2 * n + 1] * st[(2 * n + 1) * 33 + i];
            sKf[l0 + i] = a;
        }
        __syncthreads();
    }
    if (tid < 64) {                          // state now = w^128
        g_wC[h * 128 + 2 * tid]     = pre;
        g_wC[h * 128 + 2 * tid + 1] = pim;
    }
    __syncthreads();
    // QT: natural k=2n Re(CB*w^(t+1)), k=2n+1 -Im; k>=128 Toeplitz; stored k-permuted
    if (tid < 64) {
        int n = tid;
        int p0 = kperm(2 * n), p1 = kperm(2 * n + 1);
        float qre = cbre * wre - cbim * wim; // CB * w^1
        float qim = cbre * wim + cbim * wre;
        for (int t = 0; t < CHK; t++) {
            g_QT[(h * CHK + t) * KC_ + p0] = tf32f(qre);
            g_QT[(h * CHK + t) * KC_ + p1] = tf32f(-qim);
            float nr = qre * wre - qim * wim;
            qim = qre * wim + qim * wre;
            qre = nr;
        }
    } else if (tid < 192) {
        int j = tid - 64;                    // 0..127
        int pj = 128 + kperm(j);
        float K0D = sKf[0] + Dv[h];
        for (int t = 0; t < CHK; t++) {
            float v = (j < t) ? sKf[t - j] : (j == t ? K0D : 0.f);
            g_QT[(h * CHK + t) * KC_ + pj] = tf32f(v);
        }
    }
}

// ---------------- LayerNorm partial sums over (L,H) per batch ----------------
__global__ __launch_bounds__(256) void k_lnpart(const float* __restrict__ x) {
    int b = blockIdx.x, s = blockIdx.y;      // 16 x 32
    const float4* p = (const float4*)(x + (size_t)b * (L_ * H_)) + (size_t)s * 4096;
    float su = 0.f, sq = 0.f;
    for (int i = threadIdx.x; i < 4096; i += 256) {
        float4 v = p[i];
        su += v.x + v.y + v.z + v.w;
        sq += v.x * v.x + v.y * v.y + v.z * v.z + v.w * v.w;
    }
    double ds = (double)su, dq = (double)sq;
    #pragma unroll
    for (int o = 16; o > 0; o >>= 1) {
        ds += __shfl_down_sync(0xffffffffu, ds, o);
        dq += __shfl_down_sync(0xffffffffu, dq, o);
    }
    __shared__ double ws[8], wq[8];
    int lane = threadIdx.x & 31, warp = threadIdx.x >> 5;
    if (lane == 0) { ws[warp] = ds; wq[warp] = dq; }
    __syncthreads();
    if (threadIdx.x == 0) {
        double S = 0, Q = 0;
        for (int i = 0; i < 8; i++) { S += ws[i]; Q += wq[i]; }
        g_part[(b * 32 + s) * 2]     = S;
        g_part[(b * 32 + s) * 2 + 1] = Q;
    }
}

// ---------------- normalize + transpose into g_U (tf32); LN-final folded in ----------------
__global__ __launch_bounds__(128) void k_xpose(const float* __restrict__ x) {
    int b = blockIdx.x, j = blockIdx.y;
    int tid = threadIdx.x;                   // 128
    __shared__ float sx[32 * 129];
    __shared__ float sms[2];
    if (tid < 32) {
        double s = g_part[(b * 32 + tid) * 2];
        double q = g_part[(b * 32 + tid) * 2 + 1];
        #pragma unroll
        for (int o = 16; o > 0; o >>= 1) {
            s += __shfl_down_sync(0xffffffffu, s, o);
            q += __shfl_down_sync(0xffffffffu, q, o);
        }
        if (tid == 0) {
            double inv = 1.0 / (double)(L_ * H_);
            double mean = s * inv;
            double var  = q * inv - mean * mean;
            sms[0] = (float)mean;
            sms[1] = (float)(1.0 / sqrt(var + 1e-5));
        }
    }
    #pragma unroll 4
    for (int c = 0; c < 32; c++)
        sx[c * 129 + tid] = x[((size_t)b * L_ + (size_t)c * 128 + j) * H_ + tid];
    __syncthreads();
    float mean = sms[0], rstd = sms[1];
    int w = tid >> 5, lane = tid & 31;
    for (int h0 = w; h0 < 128; h0 += 4)
        g_U[(h0 * 128 + j) * COLS_ + b * 32 + lane] =
            tf32f((sx[lane * 129 + h0] - mean) * rstd);
}

// ---------------- tf32 GEMM panels ----------------
// float2 fragment loads from k-permuted buffers ([row*36 + k'] layout)
#define GEMM_PANEL_F2(As, Bs, acc, wm, wn, g, tg)                              \
    _Pragma("unroll")                                                          \
    for (int ks = 0; ks < 32; ks += 8) {                                       \
        unsigned a[4][4], bf[4][2];                                            \
        _Pragma("unroll")                                                      \
        for (int mt = 0; mt < 4; mt++) {                                       \
            int r = (wm) * 64 + mt * 16 + (g);                                 \
            float2 lo = *(const float2*)((const float*)(As) + r * 36 + ks + 2 * (tg)); \
            float2 hi = *(const float2*)((const float*)(As) + (r + 8) * 36 + ks + 2 * (tg)); \
            a[mt][0] = __float_as_uint(lo.x); a[mt][1] = __float_as_uint(hi.x);\
            a[mt][2] = __float_as_uint(lo.y); a[mt][3] = __float_as_uint(hi.y);\
        }                                                                      \
        _Pragma("unroll")                                                      \
        for (int nt = 0; nt < 4; nt++) {                                       \
            int nn = (wn) * 32 + nt * 8 + (g);                                 \
            float2 bv = *(const float2*)((const float*)(Bs) + nn * 36 + ks + 2 * (tg)); \
            bf[nt][0] = __float_as_uint(bv.x); bf[nt][1] = __float_as_uint(bv.y); \
        }                                                                      \
        _Pragma("unroll")                                                      \
        for (int mt = 0; mt < 4; mt++)                                         \
            _Pragma("unroll")                                                  \
            for (int nt = 0; nt < 4; nt++)                                     \
                mma8(acc[mt][nt], a[mt], bf[nt]);                              \
    }

// A from sP ([col*SPD + k] natural order), B from k-permuted buffer
#define GEMM_PANEL_SP(ko, Bs, acc, wm, wn, g, tg)                              \
    _Pragma("unroll")                                                          \
    for (int ks = 0; ks < 32; ks += 8) {                                       \
        unsigned a[4][4], bf[4][2];                                            \
        _Pragma("unroll")                                                      \
        for (int mt = 0; mt < 4; mt++) {                                       \
            int r = (wm) * 64 + mt * 16 + (g);                                 \
            a[mt][0] = __float_as_uint(sP[r * SPD + (ko) + ks + (tg)]);        \
            a[mt][1] = __float_as_uint(sP[(r + 8) * SPD + (ko) + ks + (tg)]);  \
            a[mt][2] = __float_as_uint(sP[r * SPD + (ko) + ks + (tg) + 4]);    \
            a[mt][3] = __float_as_uint(sP[(r + 8) * SPD + (ko) + ks + (tg) + 4]);\
        }                                                                      \
        _Pragma("unroll")                                                      \
        for (int nt = 0; nt < 4; nt++) {                                       \
            int nn = (wn) * 32 + nt * 8 + (g);                                 \
            float2 bv = *(const float2*)((const float*)(Bs) + nn * 36 + ks + 2 * (tg)); \
            bf[nt][0] = __float_as_uint(bv.x); bf[nt][1] = __float_as_uint(bv.y); \
        }                                                                      \
        _Pragma("unroll")                                                      \
        for (int mt = 0; mt < 4; mt++)                                         \
            _Pragma("unroll")                                                  \
            for (int nt = 0; nt < 4; nt++)                                     \
                mma8(acc[mt][nt], a[mt], bf[nt]);                              \
    }

// ---------------- fused GEMM-A + prefix scan + GEMM-C ----------------
// Us persistent (4 u panels, k-permuted fill), Ws double-buffered stream,
// 1 sync per panel; sP [col][k] natural, conflict-free.
#define SMEM_ABC ((6 * 4608) * 4 + 128 * SPD * 4)
__global__ __launch_bounds__(256) void k_gemmABC() {
    extern __shared__ unsigned smem[];
    unsigned* Us = smem;                         // [4][4608]
    unsigned* Ws = smem + 4 * 4608;              // [2][4608]
    float* sP = (float*)(smem + 6 * 4608);       // [128*SPD]
    int h = blockIdx.x >> 2, col0 = (blockIdx.x & 3) * 128;
    int tid = threadIdx.x, lane = tid & 31, warp = tid >> 5;
    int wm = warp & 1, wn = warp >> 1, g = lane >> 2, tg = lane & 3;
    const float* srcU = &g_U[h * 128 * COLS_];
    const float* srcW = &g_WAT[h * 128 * 128];
    const float* srcQ = &g_QT[h * CHK * KC_];

    uint4 raA[4];
    #define LOADW(p) { _Pragma("unroll") for (int i = 0; i < 4; i++) {         \
        int idx = tid + i * 256; int m = idx >> 3, k4 = (idx & 7) * 4;         \
        raA[i] = *(const uint4*)&srcW[m * 128 + (p) * 32 + k4]; } }
    #define LOADQ(p) { _Pragma("unroll") for (int i = 0; i < 4; i++) {         \
        int idx = tid + i * 256; int t = idx >> 3, k4 = (idx & 7) * 4;         \
        raA[i] = *(const uint4*)&srcQ[t * KC_ + (p) * 32 + k4]; } }
    #define STS_DIR(buf) { _Pragma("unroll") for (int i = 0; i < 4; i++) {     \
        int idx = tid + i * 256; int m = idx >> 3, k4 = (idx & 7) * 4;         \
        *(uint4*)&(buf)[m * 36 + k4] = raA[i]; } }

    LOADW(0);
    // ---- fill Us (k-permuted scatter), 2 panels at a time ----
    {
        uint4 t0[4], t1[4];
        #pragma unroll
        for (int pp = 0; pp < 4; pp += 2) {
            #pragma unroll
            for (int i = 0; i < 4; i++) {
                int idx = tid + i * 256; int kk = idx >> 5, c = (idx & 31) * 4;
                t0[i] = *(const uint4*)&srcU[(pp * 32 + kk) * COLS_ + col0 + c];
                t1[i] = *(const uint4*)&srcU[((pp + 1) * 32 + kk) * COLS_ + col0 + c];
            }
            #pragma unroll
            for (int i = 0; i < 4; i++) {
                int idx = tid + i * 256; int kk = idx >> 5, c = (idx & 31) * 4;
                int kkp = (kk & 24) | perm8(kk & 7);
                unsigned* U0 = Us + pp * 4608;
                unsigned* U1 = Us + (pp + 1) * 4608;
                U0[c * 36 + kkp] = t0[i].x; U0[(c + 1) * 36 + kkp] = t0[i].y;
                U0[(c + 2) * 36 + kkp] = t0[i].z; U0[(c + 3) * 36 + kkp] = t0[i].w;
                U1[c * 36 + kkp] = t1[i].x; U1[(c + 1) * 36 + kkp] = t1[i].y;
                U1[(c + 2) * 36 + kkp] = t1[i].z; U1[(c + 3) * 36 + kkp] = t1[i].w;
            }
        }
    }
    STS_DIR(Ws);                                 // WAT panel 0 -> Ws[0]
    __syncthreads();
    LOADW(1);
    float acc[4][4][4] = {};
    // ---- phase 1: P[m][col] = sum_j WAT[m][j]*u[j][col] ----
    #pragma unroll
    for (int p = 0; p < 4; p++) {
        GEMM_PANEL_F2((Ws + (p & 1) * 4608), (Us + p * 4608), acc, wm, wn, g, tg);
        if (p < 3) {
            STS_DIR((Ws + ((p + 1) & 1) * 4608));
            __syncthreads();
            if (p < 2) { LOADW(p + 2); } else { LOADQ(0); }
        }
    }
    // ---- stage P into sP[col][m] ----
    #pragma unroll
    for (int mt = 0; mt < 4; mt++)
        #pragma unroll
        for (int nt = 0; nt < 4; nt++) {
            int r0 = wm * 64 + mt * 16 + g;
            int cl = wn * 32 + nt * 8 + 2 * tg;
            sP[cl * SPD + r0]           = acc[mt][nt][0];
            sP[(cl + 1) * SPD + r0]     = acc[mt][nt][1];
            sP[cl * SPD + r0 + 8]       = acc[mt][nt][2];
            sP[(cl + 1) * SPD + r0 + 8] = acc[mt][nt][3];
        }
    __syncthreads();
    STS_DIR(Ws);                                 // QT panel 0 -> Ws[0]
    // ---- prefix scan over 32 chunks ----
    {
        int n = tid & 63, bl = tid >> 6;
        float wre = g_wC[h * 128 + 2 * n], wim = g_wC[h * 128 + 2 * n + 1];
        float sre = 0.f, sim = 0.f;
        #pragma unroll 4
        for (int c = 0; c < 32; c++) {
            int colI = bl * 32 + c;
            float2 pv = *(float2*)&sP[colI * SPD + 2 * n];
            *(float2*)&sP[colI * SPD + 2 * n] = make_float2(tf32f(sre), tf32f(sim));
            float nr = wre * sre - wim * sim + pv.x;
            sim = wre * sim + wim * sre + pv.y;
            sre = nr;
        }
    }
    __syncthreads();
    LOADQ(1);
    // ---- phase 2: G[col][t] = gelu( sum_k [Sin;u](k,col) * QT[t][k] ) ----
    #pragma unroll
    for (int mt = 0; mt < 4; mt++)
        #pragma unroll
        for (int nt = 0; nt < 4; nt++)
            #pragma unroll
            for (int q = 0; q < 4; q++) acc[mt][nt][q] = 0.f;
    #pragma unroll
    for (int p = 0; p < 8; p++) {
        if (p < 4) { GEMM_PANEL_SP(p * 32, (Ws + (p & 1) * 4608), acc, wm, wn, g, tg); }
        else       { GEMM_PANEL_F2((Us + (p - 4) * 4608), (Ws + (p & 1) * 4608), acc, wm, wn, g, tg); }
        if (p < 7) {
            STS_DIR((Ws + ((p + 1) & 1) * 4608));
            __syncthreads();
            if (p < 6) LOADQ(p + 2);
        }
    }
    // ---- epilogue: GELU, write G[h][col][t] ----
    float* Gd = &g_G[h * COLS_ * CHK];
    #pragma unroll
    for (int mt = 0; mt < 4; mt++)
        #pragma unroll
        for (int nt = 0; nt < 4; nt++) {
            int r0 = col0 + wm * 64 + mt * 16 + g;   // col
            int c = wn * 32 + nt * 8 + 2 * tg;       // t
            *(float2*)&Gd[r0 * CHK + c] =
                make_float2(tf32f(gelu_f(acc[mt][nt][0])), tf32f(gelu_f(acc[mt][nt][1])));
            *(float2*)&Gd[(r0 + 8) * CHK + c] =
                make_float2(tf32f(gelu_f(acc[mt][nt][2])), tf32f(gelu_f(acc[mt][nt][3])));
        }
    #undef LOADW
    #undef LOADQ
    #undef STS_DIR
}

// ---------------- GEMM-D: out[t][o] = sum_h G[h][col][t] * W1[o][h] + b1 + x ----------------
// double-buffered, 1 sync/panel, 2 CTAs/SM, k-permuted fills + float2 reads
#define SMEM_D (4 * 4608 * 4)
__global__ __launch_bounds__(256, 2) void k_gemmD(const float* __restrict__ x,
                                                  const float* __restrict__ W1,
                                                  const float* __restrict__ b1,
                                                  float* __restrict__ out) {
    extern __shared__ unsigned dsm[];
    // layout: A0, A1, B0, B1 (each 4608)
    int col = blockIdx.x;                    // (b,c)
    int b = col >> 5, c = col & 31;
    int tid = threadIdx.x, lane = tid & 31, warp = tid >> 5;
    int wm = warp & 1, wn = warp >> 1, g = lane >> 2, tg = lane & 3;
    float acc[4][4][4] = {};
    uint4 ra[4], rb[4];

    #define GDL(h0) {                                                          \
        _Pragma("unroll") for (int i = 0; i < 4; i++) {                        \
            int idx = tid + i * 256; int kk = idx >> 5, t4 = (idx & 31) * 4;   \
            ra[i] = *(const uint4*)&g_G[(((h0) + kk) * COLS_ + col) * CHK + t4]; } \
        _Pragma("unroll") for (int i = 0; i < 4; i++) {                        \
            int idx = tid + i * 256; int o = idx >> 3, k4 = (idx & 7) * 4;     \
            float4 v = *(const float4*)&W1[o * H_ + (h0) + k4];                \
            rb[i].x = f2tf(v.x); rb[i].y = f2tf(v.y);                          \
            rb[i].z = f2tf(v.z); rb[i].w = f2tf(v.w); } }
    #define GDS(buf) {                                                         \
        unsigned* Ab = dsm + (buf) * 4608;                                     \
        unsigned* Bb = dsm + 2 * 4608 + (buf) * 4608;                          \
        _Pragma("unroll") for (int i = 0; i < 4; i++) {                        \
            int idx = tid + i * 256; int kk = idx >> 5, t4 = (idx & 31) * 4;   \
            int kkp = (kk & 24) | perm8(kk & 7);                               \
            Ab[t4 * 36 + kkp] = ra[i].x; Ab[(t4 + 1) * 36 + kkp] = ra[i].y;    \
            Ab[(t4 + 2) * 36 + kkp] = ra[i].z; Ab[(t4 + 3) * 36 + kkp] = ra[i].w; } \
        _Pragma("unroll") for (int i = 0; i < 4; i++) {                        \
            int idx = tid + i * 256; int o = idx >> 3, k4 = (idx & 7) * 4;     \
            int base = o * 36 + (k4 & ~7) + ((k4 >> 2) & 1);                   \
            Bb[base] = rb[i].x; Bb[base + 2] = rb[i].y;                        \
            Bb[base + 4] = rb[i].z; Bb[base + 6] = rb[i].w; } }

    GDL(0); GDS(0);
    __syncthreads();
    GDL(32);
    #pragma unroll
    for (int p = 0; p < 4; p++) {
        GEMM_PANEL_F2((dsm + (p & 1) * 4608), (dsm + 2 * 4608 + (p & 1) * 4608),
                      acc, wm, wn, g, tg);
        if (p < 3) {
            GDS((p + 1) & 1);
            __syncthreads();
            if (p < 2) GDL((p + 2) * 32);
        }
    }
    #pragma unroll
    for (int mt = 0; mt < 4; mt++)
        #pragma unroll
        for (int nt = 0; nt < 4; nt++) {
            int t0 = wm * 64 + mt * 16 + g;
            int o  = wn * 32 + nt * 8 + 2 * tg;
            float2 bias = *(const float2*)&b1[o];
            size_t base0 = ((size_t)b * L_ + c * 128 + t0) * H_ + o;
            size_t base1 = ((size_t)b * L_ + c * 128 + t0 + 8) * H_ + o;
            float2 x0 = *(const float2*)&x[base0];
            float2 x1 = *(const float2*)&x[base1];
            *(float2*)&out[base0] = make_float2(acc[mt][nt][0] + bias.x + x0.x,
                                                acc[mt][nt][1] + bias.y + x0.y);
            *(float2*)&out[base1] = make_float2(acc[mt][nt][2] + bias.x + x1.x,
                                                acc[mt][nt][3] + bias.y + x1.y);
        }
    #undef GDL
    #undef GDS
}

// ---------------- launch ----------------
extern "C" void kernel_launch(void* const* d_in, const int* in_sizes, int n_in,
                              void* d_out, int out_size) {
    const float* x     = (const float*)d_in[0];
    const float* Are   = (const float*)d_in[1];
    const float* Aim   = (const float*)d_in[2];
    const float* Bre   = (const float*)d_in[3];
    const float* Bim   = (const float*)d_in[4];
    const float* Cre   = (const float*)d_in[5];
    const float* Cim   = (const float*)d_in[6];
    const float* Dv    = (const float*)d_in[7];
    const float* logdt = (const float*)d_in[8];
    const float* W1    = (const float*)d_in[9];
    const float* b1    = (const float*)d_in[10];
    float* out = (float*)d_out;

    cudaFuncSetAttribute(k_gemmABC, cudaFuncAttributeMaxDynamicSharedMemorySize, SMEM_ABC);
    cudaFuncSetAttribute(k_gemmD, cudaFuncAttributeMaxDynamicSharedMemorySize, SMEM_D);

    k_powQT<<<H_, 256>>>(Are, Aim, Bre, Bim, Cre, Cim, logdt, Dv);
    k_lnpart<<<dim3(B_, 32), 256>>>(x);
    k_xpose<<<dim3(B_, CHK), 128>>>(x);
    k_gemmABC<<<H_ * 4, 256, SMEM_ABC>>>();
    k_gemmD<<<COLS_, 256, SMEM_D>>>(x, W1, b1, out);
}

// round 10
// speedup vs baseline: 1.0287x; 1.0072x over previous
#include <cuda_runtime.h>
#include <math.h>

// Problem dims
#define H_    128
#define B_    16
#define L_    4096
#define SN    64      // SSM state size N
#define CHK   128     // chunk length
#define NCH   32      // chunks (L/CHK)
#define COLS_ 512     // B_*NCH
#define KC_   256     // GEMM-C K dim (2*SN + CHK)
#define SPD   132     // sP stride ([col][k] layout, conflict-free)

// ---------------- device scratch ----------------
static __device__ __align__(16) float g_wC [H_ * 128];         // [h][2n] w^128
static __device__ __align__(16) float g_WAT[H_ * 128 * 128];   // [h][m][j'] k-permuted, tf32
static __device__ __align__(16) float g_QT [H_ * CHK * KC_];   // [h][t][k'] k-permuted, tf32
static __device__ __align__(16) float g_U  [H_ * 128 * COLS_]; // [h][j][col] u, tf32 (natural)
static __device__ __align__(16) float g_G  [H_ * COLS_ * CHK]; // [h][col][t] tf32 (natural)
static __device__ double g_part[B_ * 32 * 2];

__device__ __forceinline__ float gelu_f(float v) {
    return 0.5f * v * (1.0f + erff(v * 0.70710678118654752f));
}
__device__ __forceinline__ unsigned f2tf(float f) {
    unsigned u; asm("cvt.rna.tf32.f32 %0, %1;" : "=r"(u) : "f"(f)); return u;
}
__device__ __forceinline__ float tf32f(float f) { return __uint_as_float(f2tf(f)); }
// within-8 k permutation: [k0,k4,k1,k5,k2,k6,k3,k7]
__device__ __forceinline__ int perm8(int j) { return ((j & 3) << 1) | ((j >> 2) & 1); }
__device__ __forceinline__ int kperm(int k) { return (k & ~7) | perm8(k & 7); }

__device__ __forceinline__ void mma8(float* d, const unsigned* a, const unsigned* b) {
    asm volatile("mma.sync.aligned.m16n8k8.row.col.f32.tf32.tf32.f32 "
        "{%0,%1,%2,%3}, {%4,%5,%6,%7}, {%8,%9}, {%0,%1,%2,%3};"
        : "+f"(d[0]), "+f"(d[1]), "+f"(d[2]), "+f"(d[3])
        : "r"(a[0]), "r"(a[1]), "r"(a[2]), "r"(a[3]), "r"(b[0]), "r"(b[1]));
}

// ---------------- precompute: powers + WAT + K + QT (k-permuted outputs) ----------------
__global__ __launch_bounds__(256) void k_powQT(
                      const float* __restrict__ Are, const float* __restrict__ Aim,
                      const float* __restrict__ Bre, const float* __restrict__ Bim,
                      const float* __restrict__ Cre, const float* __restrict__ Cim,
                      const float* __restrict__ logdt, const float* __restrict__ Dv) {
    int h = blockIdx.x, tid = threadIdx.x;   // 256 threads
    __shared__ float st[128 * 33];           // power tile [chan][i]
    __shared__ float scb[128];
    __shared__ float sKf[128];
    float pre = 0.f, pim = 0.f, wre = 0.f, wim = 0.f, cbre = 0.f, cbim = 0.f;
    if (tid < 64) {
        int n = tid, hn = h * SN + n;
        float dt = expf(logdt[h]);
        float are = Are[hn] * dt, aim = Aim[hn] * dt;
        float mag = expf(are);
        float s, c; sincosf(aim, &s, &c);
        wre = mag * c; wim = mag * s;        // w = exp(dt*A)
        cbre = (Cre[hn] * Bre[hn] - Cim[hn] * Bim[hn]) * dt;
        cbim = (Cre[hn] * Bim[hn] + Cim[hn] * Bre[hn]) * dt;
        scb[2 * n] = cbre; scb[2 * n + 1] = cbim;
        pre = 1.f; pim = 0.f;
    }
    __syncthreads();
    for (int l0 = 0; l0 < 128; l0 += 32) {
        if (tid < 64) {
            int n = tid;
            #pragma unroll 8
            for (int i = 0; i < 32; i++) {
                st[(2 * n) * 33 + i]     = pre;
                st[(2 * n + 1) * 33 + i] = pim;
                float nr = wre * pre - wim * pim;
                pim = wre * pim + wim * pre;
                pre = nr;
            }
        }
        __syncthreads();
        // WAT row m = chan (2n re / 2n+1 im), column kperm(127-l)
        for (int idx = tid; idx < 4096; idx += 256) {
            int chan = idx >> 5, i = idx & 31;
            g_WAT[(h * 128 + chan) * 128 + kperm(127 - (l0 + i))] = tf32f(st[chan * 33 + i]);
        }
        if (tid >= 64 && tid < 96) {
            int i = tid - 64;
            float a = 0.f;
            #pragma unroll 8
            for (int n = 0; n < 64; n++)
                a += scb[2 * n] * st[(2 * n) * 33 + i]
                   - scb[2 * n + 1] * st[(2 * n + 1) * 33 + i];
            sKf[l0 + i] = a;
        }
        __syncthreads();
    }
    if (tid < 64) {                          // state now = w^128
        g_wC[h * 128 + 2 * tid]     = pre;
        g_wC[h * 128 + 2 * tid + 1] = pim;
    }
    __syncthreads();
    // QT: natural k=2n Re(CB*w^(t+1)), k=2n+1 -Im; k>=128 Toeplitz; stored k-permuted
    if (tid < 64) {
        int n = tid;
        int p0 = kperm(2 * n), p1 = kperm(2 * n + 1);
        float qre = cbre * wre - cbim * wim; // CB * w^1
        float qim = cbre * wim + cbim * wre;
        for (int t = 0; t < CHK; t++) {
            g_QT[(h * CHK + t) * KC_ + p0] = tf32f(qre);
            g_QT[(h * CHK + t) * KC_ + p1] = tf32f(-qim);
            float nr = qre * wre - qim * wim;
            qim = qre * wim + qim * wre;
            qre = nr;
        }
    } else if (tid < 192) {
        int j = tid - 64;                    // 0..127
        int pj = 128 + kperm(j);
        float K0D = sKf[0] + Dv[h];
        for (int t = 0; t < CHK; t++) {
            float v = (j < t) ? sKf[t - j] : (j == t ? K0D : 0.f);
            g_QT[(h * CHK + t) * KC_ + pj] = tf32f(v);
        }
    }
}

// ---------------- LayerNorm partial sums over (L,H) per batch ----------------
__global__ __launch_bounds__(256) void k_lnpart(const float* __restrict__ x) {
    int b = blockIdx.x, s = blockIdx.y;      // 16 x 32
    const float4* p = (const float4*)(x + (size_t)b * (L_ * H_)) + (size_t)s * 4096;
    float su = 0.f, sq = 0.f;
    for (int i = threadIdx.x; i < 4096; i += 256) {
        float4 v = p[i];
        su += v.x + v.y + v.z + v.w;
        sq += v.x * v.x + v.y * v.y + v.z * v.z + v.w * v.w;
    }
    double ds = (double)su, dq = (double)sq;
    #pragma unroll
    for (int o = 16; o > 0; o >>= 1) {
        ds += __shfl_down_sync(0xffffffffu, ds, o);
        dq += __shfl_down_sync(0xffffffffu, dq, o);
    }
    __shared__ double ws[8], wq[8];
    int lane = threadIdx.x & 31, warp = threadIdx.x >> 5;
    if (lane == 0) { ws[warp] = ds; wq[warp] = dq; }
    __syncthreads();
    if (threadIdx.x == 0) {
        double S = 0, Q = 0;
        for (int i = 0; i < 8; i++) { S += ws[i]; Q += wq[i]; }
        g_part[(b * 32 + s) * 2]     = S;
        g_part[(b * 32 + s) * 2 + 1] = Q;
    }
}

// ---------------- normalize + transpose into g_U (tf32); LN-final folded in ----------------
__global__ __launch_bounds__(128) void k_xpose(const float* __restrict__ x) {
    int b = blockIdx.x, j = blockIdx.y;
    int tid = threadIdx.x;                   // 128
    __shared__ float sx[32 * 129];
    __shared__ float sms[2];
    if (tid < 32) {
        double s = g_part[(b * 32 + tid) * 2];
        double q = g_part[(b * 32 + tid) * 2 + 1];
        #pragma unroll
        for (int o = 16; o > 0; o >>= 1) {
            s += __shfl_down_sync(0xffffffffu, s, o);
            q += __shfl_down_sync(0xffffffffu, q, o);
        }
        if (tid == 0) {
            double inv = 1.0 / (double)(L_ * H_);
            double mean = s * inv;
            double var  = q * inv - mean * mean;
            sms[0] = (float)mean;
            sms[1] = (float)(1.0 / sqrt(var + 1e-5));
        }
    }
    #pragma unroll 4
    for (int c = 0; c < 32; c++)
        sx[c * 129 + tid] = x[((size_t)b * L_ + (size_t)c * 128 + j) * H_ + tid];
    __syncthreads();
    float mean = sms[0], rstd = sms[1];
    int w = tid >> 5, lane = tid & 31;
    for (int h0 = w; h0 < 128; h0 += 4)
        g_U[(h0 * 128 + j) * COLS_ + b * 32 + lane] =
            tf32f((sx[lane * 129 + h0] - mean) * rstd);
}

// ---------------- tf32 GEMM panels ----------------
// float2 fragment loads from k-permuted buffers ([row*36 + k'] layout)
#define GEMM_PANEL_F2(As, Bs, acc, wm, wn, g, tg)                              \
    _Pragma("unroll")                                                          \
    for (int ks = 0; ks < 32; ks += 8) {                                       \
        unsigned a[4][4], bf[4][2];                                            \
        _Pragma("unroll")                                                      \
        for (int mt = 0; mt < 4; mt++) {                                       \
            int r = (wm) * 64 + mt * 16 + (g);                                 \
            float2 lo = *(const float2*)((const float*)(As) + r * 36 + ks + 2 * (tg)); \
            float2 hi = *(const float2*)((const float*)(As) + (r + 8) * 36 + ks + 2 * (tg)); \
            a[mt][0] = __float_as_uint(lo.x); a[mt][1] = __float_as_uint(hi.x);\
            a[mt][2] = __float_as_uint(lo.y); a[mt][3] = __float_as_uint(hi.y);\
        }                                                                      \
        _Pragma("unroll")                                                      \
        for (int nt = 0; nt < 4; nt++) {                                       \
            int nn = (wn) * 32 + nt * 8 + (g);                                 \
            float2 bv = *(const float2*)((const float*)(Bs) + nn * 36 + ks + 2 * (tg)); \
            bf[nt][0] = __float_as_uint(bv.x); bf[nt][1] = __float_as_uint(bv.y); \
        }                                                                      \
        _Pragma("unroll")                                                      \
        for (int mt = 0; mt < 4; mt++)                                         \
            _Pragma("unroll")                                                  \
            for (int nt = 0; nt < 4; nt++)                                     \
                mma8(acc[mt][nt], a[mt], bf[nt]);                              \
    }

// A from sP ([col*SPD + k] natural order), B from k-permuted buffer
#define GEMM_PANEL_SP(ko, Bs, acc, wm, wn, g, tg)                              \
    _Pragma("unroll")                                                          \
    for (int ks = 0; ks < 32; ks += 8) {                                       \
        unsigned a[4][4], bf[4][2];                                            \
        _Pragma("unroll")                                                      \
        for (int mt = 0; mt < 4; mt++) {                                       \
            int r = (wm) * 64 + mt * 16 + (g);                                 \
            a[mt][0] = __float_as_uint(sP[r * SPD + (ko) + ks + (tg)]);        \
            a[mt][1] = __float_as_uint(sP[(r + 8) * SPD + (ko) + ks + (tg)]);  \
            a[mt][2] = __float_as_uint(sP[r * SPD + (ko) + ks + (tg) + 4]);    \
            a[mt][3] = __float_as_uint(sP[(r + 8) * SPD + (ko) + ks + (tg) + 4]);\
        }                                                                      \
        _Pragma("unroll")                                                      \
        for (int nt = 0; nt < 4; nt++) {                                       \
            int nn = (wn) * 32 + nt * 8 + (g);                                 \
            float2 bv = *(const float2*)((const float*)(Bs) + nn * 36 + ks + 2 * (tg)); \
            bf[nt][0] = __float_as_uint(bv.x); bf[nt][1] = __float_as_uint(bv.y); \
        }                                                                      \
        _Pragma("unroll")                                                      \
        for (int mt = 0; mt < 4; mt++)                                         \
            _Pragma("unroll")                                                  \
            for (int nt = 0; nt < 4; nt++)                                     \
                mma8(acc[mt][nt], a[mt], bf[nt]);                              \
    }

// ---------------- fused GEMM-A + prefix scan + GEMM-C ----------------
// R6 pipeline: load(p+1) BEFORE compute(p), store after, 1 sync/panel.
// Us persistent (k-permuted), Ws double-buffered; sP [col][k] conflict-free.
#define SMEM_ABC ((6 * 4608) * 4 + 128 * SPD * 4)
__global__ __launch_bounds__(256) void k_gemmABC() {
    extern __shared__ unsigned smem[];
    unsigned* Us = smem;                         // [4][4608]
    unsigned* Ws = smem + 4 * 4608;              // [2][4608]
    float* sP = (float*)(smem + 6 * 4608);       // [128*SPD]
    int h = blockIdx.x >> 2, col0 = (blockIdx.x & 3) * 128;
    int tid = threadIdx.x, lane = tid & 31, warp = tid >> 5;
    int wm = warp & 1, wn = warp >> 1, g = lane >> 2, tg = lane & 3;
    const float* srcU = &g_U[h * 128 * COLS_];
    const float* srcW = &g_WAT[h * 128 * 128];
    const float* srcQ = &g_QT[h * CHK * KC_];

    uint4 raA[4];
    #define LOADW(p) { _Pragma("unroll") for (int i = 0; i < 4; i++) {         \
        int idx = tid + i * 256; int m = idx >> 3, k4 = (idx & 7) * 4;         \
        raA[i] = *(const uint4*)&srcW[m * 128 + (p) * 32 + k4]; } }
    #define LOADQ(p) { _Pragma("unroll") for (int i = 0; i < 4; i++) {         \
        int idx = tid + i * 256; int t = idx >> 3, k4 = (idx & 7) * 4;         \
        raA[i] = *(const uint4*)&srcQ[t * KC_ + (p) * 32 + k4]; } }
    #define STS_DIR(buf) { _Pragma("unroll") for (int i = 0; i < 4; i++) {     \
        int idx = tid + i * 256; int m = idx >> 3, k4 = (idx & 7) * 4;         \
        *(uint4*)&(buf)[m * 36 + k4] = raA[i]; } }

    LOADW(0);
    // ---- fill Us (k-permuted scatter), 2 panels at a time ----
    {
        uint4 t0[4], t1[4];
        #pragma unroll
        for (int pp = 0; pp < 4; pp += 2) {
            #pragma unroll
            for (int i = 0; i < 4; i++) {
                int idx = tid + i * 256; int kk = idx >> 5, c = (idx & 31) * 4;
                t0[i] = *(const uint4*)&srcU[(pp * 32 + kk) * COLS_ + col0 + c];
                t1[i] = *(const uint4*)&srcU[((pp + 1) * 32 + kk) * COLS_ + col0 + c];
            }
            #pragma unroll
            for (int i = 0; i < 4; i++) {
                int idx = tid + i * 256; int kk = idx >> 5, c = (idx & 31) * 4;
                int kkp = (kk & 24) | perm8(kk & 7);
                unsigned* U0 = Us + pp * 4608;
                unsigned* U1 = Us + (pp + 1) * 4608;
                U0[c * 36 + kkp] = t0[i].x; U0[(c + 1) * 36 + kkp] = t0[i].y;
                U0[(c + 2) * 36 + kkp] = t0[i].z; U0[(c + 3) * 36 + kkp] = t0[i].w;
                U1[c * 36 + kkp] = t1[i].x; U1[(c + 1) * 36 + kkp] = t1[i].y;
                U1[(c + 2) * 36 + kkp] = t1[i].z; U1[(c + 3) * 36 + kkp] = t1[i].w;
            }
        }
    }
    STS_DIR(Ws);                                 // WAT panel 0 -> Ws[0]
    __syncthreads();
    float acc[4][4][4] = {};
    // ---- phase 1: P[m][col] = sum_j WAT[m][j]*u[j][col] ----
    #pragma unroll
    for (int p = 0; p < 4; p++) {
        if (p < 3) { LOADW(p + 1); } else { LOADQ(0); }   // load BEFORE compute
        GEMM_PANEL_F2((Ws + (p & 1) * 4608), (Us + p * 4608), acc, wm, wn, g, tg);
        if (p < 3) {
            STS_DIR((Ws + ((p + 1) & 1) * 4608));
            __syncthreads();
        }
    }
    // ---- stage P into sP[col][m] ----
    #pragma unroll
    for (int mt = 0; mt < 4; mt++)
        #pragma unroll
        for (int nt = 0; nt < 4; nt++) {
            int r0 = wm * 64 + mt * 16 + g;
            int cl = wn * 32 + nt * 8 + 2 * tg;
            sP[cl * SPD + r0]           = acc[mt][nt][0];
            sP[(cl + 1) * SPD + r0]     = acc[mt][nt][1];
            sP[cl * SPD + r0 + 8]       = acc[mt][nt][2];
            sP[(cl + 1) * SPD + r0 + 8] = acc[mt][nt][3];
        }
    __syncthreads();
    STS_DIR(Ws);                                 // QT panel 0 -> Ws[0] (raA from LOADQ(0))
    // ---- prefix scan over 32 chunks (hides the QT store latency) ----
    {
        int n = tid & 63, bl = tid >> 6;
        float wre = g_wC[h * 128 + 2 * n], wim = g_wC[h * 128 + 2 * n + 1];
        float sre = 0.f, sim = 0.f;
        #pragma unroll 4
        for (int c = 0; c < 32; c++) {
            int colI = bl * 32 + c;
            float2 pv = *(float2*)&sP[colI * SPD + 2 * n];
            *(float2*)&sP[colI * SPD + 2 * n] = make_float2(tf32f(sre), tf32f(sim));
            float nr = wre * sre - wim * sim + pv.x;
            sim = wre * sim + wim * sre + pv.y;
            sre = nr;
        }
    }
    __syncthreads();
    // ---- phase 2: G[col][t] = gelu( sum_k [Sin;u](k,col) * QT[t][k] ) ----
    #pragma unroll
    for (int mt = 0; mt < 4; mt++)
        #pragma unroll
        for (int nt = 0; nt < 4; nt++)
            #pragma unroll
            for (int q = 0; q < 4; q++) acc[mt][nt][q] = 0.f;
    #pragma unroll
    for (int p = 0; p < 8; p++) {
        if (p < 7) LOADQ(p + 1);                 // load BEFORE compute
        if (p < 4) { GEMM_PANEL_SP(p * 32, (Ws + (p & 1) * 4608), acc, wm, wn, g, tg); }
        else       { GEMM_PANEL_F2((Us + (p - 4) * 4608), (Ws + (p & 1) * 4608), acc, wm, wn, g, tg); }
        if (p < 7) {
            STS_DIR((Ws + ((p + 1) & 1) * 4608));
            __syncthreads();
        }
    }
    // ---- epilogue: GELU, write G[h][col][t] ----
    float* Gd = &g_G[h * COLS_ * CHK];
    #pragma unroll
    for (int mt = 0; mt < 4; mt++)
        #pragma unroll
        for (int nt = 0; nt < 4; nt++) {
            int r0 = col0 + wm * 64 + mt * 16 + g;   // col
            int c = wn * 32 + nt * 8 + 2 * tg;       // t
            *(float2*)&Gd[r0 * CHK + c] =
                make_float2(tf32f(gelu_f(acc[mt][nt][0])), tf32f(gelu_f(acc[mt][nt][1])));
            *(float2*)&Gd[(r0 + 8) * CHK + c] =
                make_float2(tf32f(gelu_f(acc[mt][nt][2])), tf32f(gelu_f(acc[mt][nt][3])));
        }
    #undef LOADW
    #undef LOADQ
    #undef STS_DIR
}

// ---------------- GEMM-D: out[t][o] = sum_h G[h][col][t] * W1[o][h] + b1 + x ----------------
// double-buffered, load-before-compute, 1 sync/panel, 2 CTAs/SM
#define SMEM_D (4 * 4608 * 4)
__global__ __launch_bounds__(256, 2) void k_gemmD(const float* __restrict__ x,
                                                  const float* __restrict__ W1,
                                                  const float* __restrict__ b1,
                                                  float* __restrict__ out) {
    extern __shared__ unsigned dsm[];
    // layout: A0, A1, B0, B1 (each 4608)
    int col = blockIdx.x;                    // (b,c)
    int b = col >> 5, c = col & 31;
    int tid = threadIdx.x, lane = tid & 31, warp = tid >> 5;
    int wm = warp & 1, wn = warp >> 1, g = lane >> 2, tg = lane & 3;
    float acc[4][4][4] = {};
    uint4 ra[4], rb[4];

    #define GDL(h0) {                                                          \
        _Pragma("unroll") for (int i = 0; i < 4; i++) {                        \
            int idx = tid + i * 256; int kk = idx >> 5, t4 = (idx & 31) * 4;   \
            ra[i] = *(const uint4*)&g_G[(((h0) + kk) * COLS_ + col) * CHK + t4]; } \
        _Pragma("unroll") for (int i = 0; i < 4; i++) {                        \
            int idx = tid + i * 256; int o = idx >> 3, k4 = (idx & 7) * 4;     \
            float4 v = *(const float4*)&W1[o * H_ + (h0) + k4];                \
            rb[i].x = f2tf(v.x); rb[i].y = f2tf(v.y);                          \
            rb[i].z = f2tf(v.z); rb[i].w = f2tf(v.w); } }
    #define GDS(buf) {                                                         \
        unsigned* Ab = dsm + (buf) * 4608;                                     \
        unsigned* Bb = dsm + 2 * 4608 + (buf) * 4608;                          \
        _Pragma("unroll") for (int i = 0; i < 4; i++) {                        \
            int idx = tid + i * 256; int kk = idx >> 5, t4 = (idx & 31) * 4;   \
            int kkp = (kk & 24) | perm8(kk & 7);                               \
            Ab[t4 * 36 + kkp] = ra[i].x; Ab[(t4 + 1) * 36 + kkp] = ra[i].y;    \
            Ab[(t4 + 2) * 36 + kkp] = ra[i].z; Ab[(t4 + 3) * 36 + kkp] = ra[i].w; } \
        _Pragma("unroll") for (int i = 0; i < 4; i++) {                        \
            int idx = tid + i * 256; int o = idx >> 3, k4 = (idx & 7) * 4;     \
            int base = o * 36 + (k4 & ~7) + ((k4 >> 2) & 1);                   \
            Bb[base] = rb[i].x; Bb[base + 2] = rb[i].y;                        \
            Bb[base + 4] = rb[i].z; Bb[base + 6] = rb[i].w; } }

    GDL(0); GDS(0);
    __syncthreads();
    #pragma unroll
    for (int p = 0; p < 4; p++) {
        if (p < 3) GDL((p + 1) * 32);            // load BEFORE compute
        GEMM_PANEL_F2((dsm + (p & 1) * 4608), (dsm + 2 * 4608 + (p & 1) * 4608),
                      acc, wm, wn, g, tg);
        if (p < 3) {
            GDS((p + 1) & 1);
            __syncthreads();
        }
    }
    #pragma unroll
    for (int mt = 0; mt < 4; mt++)
        #pragma unroll
        for (int nt = 0; nt < 4; nt++) {
            int t0 = wm * 64 + mt * 16 + g;
            int o  = wn * 32 + nt * 8 + 2 * tg;
            float2 bias = *(const float2*)&b1[o];
            size_t base0 = ((size_t)b * L_ + c * 128 + t0) * H_ + o;
            size_t base1 = ((size_t)b * L_ + c * 128 + t0 + 8) * H_ + o;
            float2 x0 = *(const float2*)&x[base0];
            float2 x1 = *(const float2*)&x[base1];
            *(float2*)&out[base0] = make_float2(acc[mt][nt][0] + bias.x + x0.x,
                                                acc[mt][nt][1] + bias.y + x0.y);
            *(float2*)&out[base1] = make_float2(acc[mt][nt][2] + bias.x + x1.x,
                                                acc[mt][nt][3] + bias.y + x1.y);
        }
    #undef GDL
    #undef GDS
}

// ---------------- launch ----------------
extern "C" void kernel_launch(void* const* d_in, const int* in_sizes, int n_in,
                              void* d_out, int out_size) {
    const float* x     = (const float*)d_in[0];
    const float* Are   = (const float*)d_in[1];
    const float* Aim   = (const float*)d_in[2];
    const float* Bre   = (const float*)d_in[3];
    const float* Bim   = (const float*)d_in[4];
    const float* Cre   = (const float*)d_in[5];
    const float* Cim   = (const float*)d_in[6];
    const float* Dv    = (const float*)d_in[7];
    const float* logdt = (const float*)d_in[8];
    const float* W1    = (const float*)d_in[9];
    const float* b1    = (const float*)d_in[10];
    float* out = (float*)d_out;

    cudaFuncSetAttribute(k_gemmABC, cudaFuncAttributeMaxDynamicSharedMemorySize, SMEM_ABC);
    cudaFuncSetAttribute(k_gemmD, cudaFuncAttributeMaxDynamicSharedMemorySize, SMEM_D);

    k_powQT<<<H_, 256>>>(Are, Aim, Bre, Bim, Cre, Cim, logdt, Dv);
    k_lnpart<<<dim3(B_, 32), 256>>>(x);
    k_xpose<<<dim3(B_, CHK), 128>>>(x);
    k_gemmABC<<<H_ * 4, 256, SMEM_ABC>>>();
    k_gemmD<<<COLS_, 256, SMEM_D>>>(x, W1, b1, out);
}

// round 11
// speedup vs baseline: 1.1069x; 1.0760x over previous
#include <cuda_runtime.h>
#include <math.h>

// Problem dims
#define H_    128
#define B_    16
#define L_    4096
#define SN    64      // SSM state size N
#define CHK   128     // chunk length
#define NCH   32      // chunks (L/CHK)
#define COLS_ 512     // B_*NCH
#define KC_   256     // GEMM-C K dim (2*SN + CHK)

// ---------------- device scratch ----------------
static __device__ __align__(16) float g_wC [H_ * 128];         // [h][2n] w^128
static __device__ __align__(16) float g_WAT[H_ * 128 * 128];   // [h][m][j]; m<64 Re, m>=64 Im ; tf32
static __device__ __align__(16) float g_QT [H_ * CHK * KC_];   // [h][t][k]; k<64 Re, 64..127 -Im, >=128 Toeplitz ; tf32
static __device__ __align__(16) float g_U  [H_ * 128 * COLS_]; // [h][j][col] u, tf32
static __device__ __align__(16) float g_G  [H_ * COLS_ * CHK]; // [h][col][t] tf32
static __device__ double g_part[B_ * 32 * 2];

__device__ __forceinline__ float gelu_f(float v) {
    return 0.5f * v * (1.0f + erff(v * 0.70710678118654752f));
}
__device__ __forceinline__ unsigned f2tf(float f) {
    unsigned u; asm("cvt.rna.tf32.f32 %0, %1;" : "=r"(u) : "f"(f)); return u;
}
__device__ __forceinline__ float tf32f(float f) { return __uint_as_float(f2tf(f)); }
// within-8 k permutation (used ONLY inside k_gemmD's smem fills): [k0,k4,k1,k5,k2,k6,k3,k7]
__device__ __forceinline__ int perm8(int j) { return ((j & 3) << 1) | ((j >> 2) & 1); }

__device__ __forceinline__ void mma8(float* d, const unsigned* a, const unsigned* b) {
    asm volatile("mma.sync.aligned.m16n8k8.row.col.f32.tf32.tf32.f32 "
        "{%0,%1,%2,%3}, {%4,%5,%6,%7}, {%8,%9}, {%0,%1,%2,%3};"
        : "+f"(d[0]), "+f"(d[1]), "+f"(d[2]), "+f"(d[3])
        : "r"(a[0]), "r"(a[1]), "r"(a[2]), "r"(a[3]), "r"(b[0]), "r"(b[1]));
}

// ---------------- precompute: powers + WAT + K + QT (R6 natural layouts) ----------------
__global__ __launch_bounds__(256) void k_powQT(
                      const float* __restrict__ Are, const float* __restrict__ Aim,
                      const float* __restrict__ Bre, const float* __restrict__ Bim,
                      const float* __restrict__ Cre, const float* __restrict__ Cim,
                      const float* __restrict__ logdt, const float* __restrict__ Dv) {
    int h = blockIdx.x, tid = threadIdx.x;   // 256 threads
    __shared__ float st[128 * 33];           // power tile [chan][i]
    __shared__ float scb[128];
    __shared__ float sKf[128];
    float pre = 0.f, pim = 0.f, wre = 0.f, wim = 0.f, cbre = 0.f, cbim = 0.f;
    if (tid < 64) {
        int n = tid, hn = h * SN + n;
        float dt = expf(logdt[h]);
        float are = Are[hn] * dt, aim = Aim[hn] * dt;
        float mag = expf(are);
        float s, c; sincosf(aim, &s, &c);
        wre = mag * c; wim = mag * s;        // w = exp(dt*A)
        cbre = (Cre[hn] * Bre[hn] - Cim[hn] * Bim[hn]) * dt;
        cbim = (Cre[hn] * Bim[hn] + Cim[hn] * Bre[hn]) * dt;
        scb[2 * n] = cbre; scb[2 * n + 1] = cbim;
        pre = 1.f; pim = 0.f;
    }
    __syncthreads();
    for (int l0 = 0; l0 < 128; l0 += 32) {
        if (tid < 64) {
            int n = tid;
            #pragma unroll 8
            for (int i = 0; i < 32; i++) {
                st[(2 * n) * 33 + i]     = pre;
                st[(2 * n + 1) * 33 + i] = pim;
                float nr = wre * pre - wim * pim;
                pim = wre * pim + wim * pre;
                pre = nr;
            }
        }
        __syncthreads();
        for (int idx = tid; idx < 4096; idx += 256) {
            int chan = idx >> 5, i = idx & 31;
            int m = (chan & 1) ? 64 + (chan >> 1) : (chan >> 1);
            g_WAT[(h * 128 + m) * 128 + 127 - (l0 + i)] = tf32f(st[chan * 33 + i]);
        }
        if (tid >= 64 && tid < 96) {
            int i = tid - 64;
            float a = 0.f;
            #pragma unroll 8
            for (int n = 0; n < 64; n++)
                a += scb[2 * n] * st[(2 * n) * 33 + i]
                   - scb[2 * n + 1] * st[(2 * n + 1) * 33 + i];
            sKf[l0 + i] = a;
        }
        __syncthreads();
    }
    if (tid < 64) {                          // state now = w^128
        g_wC[h * 128 + 2 * tid]     = pre;
        g_wC[h * 128 + 2 * tid + 1] = pim;
    }
    __syncthreads();
    // QT[h][t][k]: k<64 Re(CB*w^(t+1)); 64..127 -Im; k>=128 Toeplitz K
    if (tid < 64) {
        int n = tid;
        float qre = cbre * wre - cbim * wim; // CB * w^1
        float qim = cbre * wim + cbim * wre;
        for (int t = 0; t < CHK; t++) {
            g_QT[(h * CHK + t) * KC_ + n]      = tf32f(qre);
            g_QT[(h * CHK + t) * KC_ + 64 + n] = tf32f(-qim);
            float nr = qre * wre - qim * wim;
            qim = qre * wim + qim * wre;
            qre = nr;
        }
    } else if (tid < 192) {
        int j = tid - 64;                    // 0..127
        float K0D = sKf[0] + Dv[h];
        for (int t = 0; t < CHK; t++) {
            float v = (j < t) ? sKf[t - j] : (j == t ? K0D : 0.f);
            g_QT[(h * CHK + t) * KC_ + 128 + j] = tf32f(v);
        }
    }
}

// ---------------- LayerNorm partial sums over (L,H) per batch ----------------
__global__ __launch_bounds__(256) void k_lnpart(const float* __restrict__ x) {
    int b = blockIdx.x, s = blockIdx.y;      // 16 x 32
    const float4* p = (const float4*)(x + (size_t)b * (L_ * H_)) + (size_t)s * 4096;
    float su = 0.f, sq = 0.f;
    for (int i = threadIdx.x; i < 4096; i += 256) {
        float4 v = p[i];
        su += v.x + v.y + v.z + v.w;
        sq += v.x * v.x + v.y * v.y + v.z * v.z + v.w * v.w;
    }
    double ds = (double)su, dq = (double)sq;
    #pragma unroll
    for (int o = 16; o > 0; o >>= 1) {
        ds += __shfl_down_sync(0xffffffffu, ds, o);
        dq += __shfl_down_sync(0xffffffffu, dq, o);
    }
    __shared__ double ws[8], wq[8];
    int lane = threadIdx.x & 31, warp = threadIdx.x >> 5;
    if (lane == 0) { ws[warp] = ds; wq[warp] = dq; }
    __syncthreads();
    if (threadIdx.x == 0) {
        double S = 0, Q = 0;
        for (int i = 0; i < 8; i++) { S += ws[i]; Q += wq[i]; }
        g_part[(b * 32 + s) * 2]     = S;
        g_part[(b * 32 + s) * 2 + 1] = Q;
    }
}

// ---------------- normalize + transpose into g_U (tf32); LN-final folded in ----------------
__global__ __launch_bounds__(128) void k_xpose(const float* __restrict__ x) {
    int b = blockIdx.x, j = blockIdx.y;
    int tid = threadIdx.x;                   // 128
    __shared__ float sx[32 * 129];
    __shared__ float sms[2];
    if (tid < 32) {
        double s = g_part[(b * 32 + tid) * 2];
        double q = g_part[(b * 32 + tid) * 2 + 1];
        #pragma unroll
        for (int o = 16; o > 0; o >>= 1) {
            s += __shfl_down_sync(0xffffffffu, s, o);
            q += __shfl_down_sync(0xffffffffu, q, o);
        }
        if (tid == 0) {
            double inv = 1.0 / (double)(L_ * H_);
            double mean = s * inv;
            double var  = q * inv - mean * mean;
            sms[0] = (float)mean;
            sms[1] = (float)(1.0 / sqrt(var + 1e-5));
        }
    }
    #pragma unroll 4
    for (int c = 0; c < 32; c++)
        sx[c * 129 + tid] = x[((size_t)b * L_ + (size_t)c * 128 + j) * H_ + tid];
    __syncthreads();
    float mean = sms[0], rstd = sms[1];
    int w = tid >> 5, lane = tid & 31;
    for (int h0 = w; h0 < 128; h0 += 4)
        g_U[(h0 * 128 + j) * COLS_ + b * 32 + lane] =
            tf32f((sx[lane * 129 + h0] - mean) * rstd);
}

// ---------------- tf32 GEMM compute panel (scalar LDS, natural [row*36+k] layout) ----------------
#define GEMM_COMPUTE_PANEL(As, Bs, acc, wm, wn, g, tg)                         \
    _Pragma("unroll")                                                          \
    for (int ks = 0; ks < 32; ks += 8) {                                       \
        unsigned a[4][4], bf[4][2];                                            \
        _Pragma("unroll")                                                      \
        for (int mt = 0; mt < 4; mt++) {                                       \
            int r = (wm) * 64 + mt * 16 + (g);                                 \
            a[mt][0] = (As)[r * 36 + ks + (tg)];                               \
            a[mt][1] = (As)[(r + 8) * 36 + ks + (tg)];                         \
            a[mt][2] = (As)[r * 36 + ks + (tg) + 4];                           \
            a[mt][3] = (As)[(r + 8) * 36 + ks + (tg) + 4];                     \
        }                                                                      \
        _Pragma("unroll")                                                      \
        for (int nt = 0; nt < 4; nt++) {                                       \
            int nn = (wn) * 32 + nt * 8 + (g);                                 \
            bf[nt][0] = (Bs)[nn * 36 + ks + (tg)];                             \
            bf[nt][1] = (Bs)[nn * 36 + ks + (tg) + 4];                         \
        }                                                                      \
        _Pragma("unroll")                                                      \
        for (int mt = 0; mt < 4; mt++)                                         \
            _Pragma("unroll")                                                  \
            for (int nt = 0; nt < 4; nt++)                                     \
                mma8(acc[mt][nt], a[mt], bf[nt]);                              \
    }

// float2 fragment loads from k-permuted buffers (gemmD only)
#define GEMM_PANEL_F2(As, Bs, acc, wm, wn, g, tg)                              \
    _Pragma("unroll")                                                          \
    for (int ks = 0; ks < 32; ks += 8) {                                       \
        unsigned a[4][4], bf[4][2];                                            \
        _Pragma("unroll")                                                      \
        for (int mt = 0; mt < 4; mt++) {                                       \
            int r = (wm) * 64 + mt * 16 + (g);                                 \
            float2 lo = *(const float2*)((const float*)(As) + r * 36 + ks + 2 * (tg)); \
            float2 hi = *(const float2*)((const float*)(As) + (r + 8) * 36 + ks + 2 * (tg)); \
            a[mt][0] = __float_as_uint(lo.x); a[mt][1] = __float_as_uint(hi.x);\
            a[mt][2] = __float_as_uint(lo.y); a[mt][3] = __float_as_uint(hi.y);\
        }                                                                      \
        _Pragma("unroll")                                                      \
        for (int nt = 0; nt < 4; nt++) {                                       \
            int nn = (wn) * 32 + nt * 8 + (g);                                 \
            float2 bv = *(const float2*)((const float*)(Bs) + nn * 36 + ks + 2 * (tg)); \
            bf[nt][0] = __float_as_uint(bv.x); bf[nt][1] = __float_as_uint(bv.y); \
        }                                                                      \
        _Pragma("unroll")                                                      \
        for (int mt = 0; mt < 4; mt++)                                         \
            _Pragma("unroll")                                                  \
            for (int nt = 0; nt < 4; nt++)                                     \
                mma8(acc[mt][nt], a[mt], bf[nt]);                              \
    }

// A operand from sP (element (row,k) at sP[k*136 + row]; values tf32-prerounded)
#define GEMM_PANEL_SP(k0, Bs, acc, wm, wn, g, tg)                              \
    _Pragma("unroll")                                                          \
    for (int ks = 0; ks < 32; ks += 8) {                                       \
        unsigned a[4][4], bf[4][2];                                            \
        _Pragma("unroll")                                                      \
        for (int mt = 0; mt < 4; mt++) {                                       \
            int r = (wm) * 64 + mt * 16 + (g);                                 \
            a[mt][0] = __float_as_uint(sP[((k0) + ks + (tg)) * 136 + r]);      \
            a[mt][1] = __float_as_uint(sP[((k0) + ks + (tg)) * 136 + r + 8]);  \
            a[mt][2] = __float_as_uint(sP[((k0) + ks + (tg) + 4) * 136 + r]);  \
            a[mt][3] = __float_as_uint(sP[((k0) + ks + (tg) + 4) * 136 + r + 8]);\
        }                                                                      \
        _Pragma("unroll")                                                      \
        for (int nt = 0; nt < 4; nt++) {                                       \
            int nn = (wn) * 32 + nt * 8 + (g);                                 \
            bf[nt][0] = (Bs)[nn * 36 + ks + (tg)];                             \
            bf[nt][1] = (Bs)[nn * 36 + ks + (tg) + 4];                         \
        }                                                                      \
        _Pragma("unroll")                                                      \
        for (int mt = 0; mt < 4; mt++)                                         \
            _Pragma("unroll")                                                  \
            for (int nt = 0; nt < 4; nt++)                                     \
                mma8(acc[mt][nt], a[mt], bf[nt]);                              \
    }

// ---------------- fused GEMM-A + prefix scan + GEMM-C (exact R6 structure) ----------------
#define SMEM_ABC ((6 * 4608) * 4 + 128 * 136 * 4)
__global__ __launch_bounds__(256) void k_gemmABC() {
    extern __shared__ unsigned smem[];
    unsigned* Us = smem;                         // [4][4608] u panels [c*36+kk]
    unsigned* Ws = smem + 4 * 4608;              // [2][4608] double buffer
    float* sP = (float*)(smem + 6 * 4608);       // [128*136]
    int h = blockIdx.x >> 2, col0 = (blockIdx.x & 3) * 128;
    int tid = threadIdx.x, lane = tid & 31, warp = tid >> 5;
    int wm = warp & 1, wn = warp >> 1, g = lane >> 2, tg = lane & 3;
    const float* srcU = &g_U[h * 128 * COLS_];
    const float* srcW = &g_WAT[h * 128 * 128];
    const float* srcQ = &g_QT[h * CHK * KC_];

    // ---- load all 4 u panels into Us (persist whole kernel) ----
    {
        uint4 t0[4], t1[4];
        #pragma unroll
        for (int pp = 0; pp < 4; pp += 2) {
            #pragma unroll
            for (int i = 0; i < 4; i++) {
                int idx = tid + i * 256; int kk = idx >> 5, c = (idx & 31) * 4;
                t0[i] = *(const uint4*)&srcU[(pp * 32 + kk) * COLS_ + col0 + c];
                t1[i] = *(const uint4*)&srcU[((pp + 1) * 32 + kk) * COLS_ + col0 + c];
            }
            #pragma unroll
            for (int i = 0; i < 4; i++) {
                int idx = tid + i * 256; int kk = idx >> 5, c = (idx & 31) * 4;
                unsigned* U0 = Us + pp * 4608;
                unsigned* U1 = Us + (pp + 1) * 4608;
                U0[c * 36 + kk] = t0[i].x; U0[(c + 1) * 36 + kk] = t0[i].y;
                U0[(c + 2) * 36 + kk] = t0[i].z; U0[(c + 3) * 36 + kk] = t0[i].w;
                U1[c * 36 + kk] = t1[i].x; U1[(c + 1) * 36 + kk] = t1[i].y;
                U1[(c + 2) * 36 + kk] = t1[i].z; U1[(c + 3) * 36 + kk] = t1[i].w;
            }
        }
    }
    // WAT panel 0 into Ws[0]
    uint4 wa[4];
    #pragma unroll
    for (int i = 0; i < 4; i++) {
        int idx = tid + i * 256; int m = idx >> 3, k4 = (idx & 7) * 4;
        wa[i] = *(const uint4*)&srcW[m * 128 + k4];
    }
    #pragma unroll
    for (int i = 0; i < 4; i++) {
        int idx = tid + i * 256; int m = idx >> 3, k4 = (idx & 7) * 4;
        *(uint4*)&Ws[m * 36 + k4] = wa[i];
    }
    __syncthreads();

    float acc[4][4][4] = {};
    // ---- phase 1 mainloop ----
    for (int p = 0; p < 4; p++) {
        if (p < 3) {
            #pragma unroll
            for (int i = 0; i < 4; i++) {
                int idx = tid + i * 256; int m = idx >> 3, k4 = (idx & 7) * 4;
                wa[i] = *(const uint4*)&srcW[m * 128 + (p + 1) * 32 + k4];
            }
        }
        GEMM_COMPUTE_PANEL((Ws + (p & 1) * 4608), (Us + p * 4608), acc, wm, wn, g, tg);
        if (p < 3) {
            #pragma unroll
            for (int i = 0; i < 4; i++) {
                int idx = tid + i * 256; int m = idx >> 3, k4 = (idx & 7) * 4;
                *(uint4*)&Ws[((p + 1) & 1) * 4608 + m * 36 + k4] = wa[i];
            }
            __syncthreads();
        }
    }
    // ---- stage P into sP[m][col_local], stride 136 ----
    #pragma unroll
    for (int mt = 0; mt < 4; mt++)
        #pragma unroll
        for (int nt = 0; nt < 4; nt++) {
            int r0 = wm * 64 + mt * 16 + g;
            int cl = wn * 32 + nt * 8 + 2 * tg;
            sP[r0 * 136 + cl]           = acc[mt][nt][0];
            sP[r0 * 136 + cl + 1]       = acc[mt][nt][1];
            sP[(r0 + 8) * 136 + cl]     = acc[mt][nt][2];
            sP[(r0 + 8) * 136 + cl + 1] = acc[mt][nt][3];
        }
    __syncthreads();

    // ---- prefetch QT panel 0 into Ws[0] ----
    uint4 qb[4];
    #pragma unroll
    for (int i = 0; i < 4; i++) {
        int idx = tid + i * 256; int t = idx >> 3, k4 = (idx & 7) * 4;
        qb[i] = *(const uint4*)&srcQ[t * KC_ + k4];
    }
    #pragma unroll
    for (int i = 0; i < 4; i++) {
        int idx = tid + i * 256; int t = idx >> 3, k4 = (idx & 7) * 4;
        *(uint4*)&Ws[t * 36 + k4] = qb[i];
    }

    // ---- prefix scan over 32 chunks (overlapped with QT prefetch latency) ----
    {
        int n = tid & 63, bl = tid >> 6;
        float wre = g_wC[h * 128 + 2 * n], wim = g_wC[h * 128 + 2 * n + 1];
        float sre = 0.f, sim = 0.f;
        #pragma unroll 4
        for (int c = 0; c < 32; c++) {
            int colI = bl * 32 + c;
            float pr = sP[n * 136 + colI];
            float pi = sP[(64 + n) * 136 + colI];
            sP[n * 136 + colI]        = tf32f(sre);
            sP[(64 + n) * 136 + colI] = tf32f(sim);
            float nr = wre * sre - wim * sim + pr;
            sim = wre * sim + wim * sre + pi;
            sre = nr;
        }
    }
    __syncthreads();

    // ---- phase 2 mainloop ----
    #pragma unroll
    for (int mt = 0; mt < 4; mt++)
        #pragma unroll
        for (int nt = 0; nt < 4; nt++)
            #pragma unroll
            for (int q = 0; q < 4; q++) acc[mt][nt][q] = 0.f;
    for (int p = 0; p < 8; p++) {
        if (p < 7) {
            #pragma unroll
            for (int i = 0; i < 4; i++) {
                int idx = tid + i * 256; int t = idx >> 3, k4 = (idx & 7) * 4;
                qb[i] = *(const uint4*)&srcQ[t * KC_ + (p + 1) * 32 + k4];
            }
        }
        if (p < 4) {
            GEMM_PANEL_SP(p * 32, (Ws + (p & 1) * 4608), acc, wm, wn, g, tg);
        } else {
            GEMM_COMPUTE_PANEL((Us + (p - 4) * 4608), (Ws + (p & 1) * 4608), acc, wm, wn, g, tg);
        }
        if (p < 7) {
            #pragma unroll
            for (int i = 0; i < 4; i++) {
                int idx = tid + i * 256; int t = idx >> 3, k4 = (idx & 7) * 4;
                *(uint4*)&Ws[((p + 1) & 1) * 4608 + t * 36 + k4] = qb[i];
            }
            __syncthreads();
        }
    }
    // ---- epilogue: GELU, write G[h][col][t] ----
    float* Gd = &g_G[h * COLS_ * CHK];
    #pragma unroll
    for (int mt = 0; mt < 4; mt++)
        #pragma unroll
        for (int nt = 0; nt < 4; nt++) {
            int r0 = col0 + wm * 64 + mt * 16 + g;   // col
            int c = wn * 32 + nt * 8 + 2 * tg;       // t
            *(float2*)&Gd[r0 * CHK + c] =
                make_float2(tf32f(gelu_f(acc[mt][nt][0])), tf32f(gelu_f(acc[mt][nt][1])));
            *(float2*)&Gd[(r0 + 8) * CHK + c] =
                make_float2(tf32f(gelu_f(acc[mt][nt][2])), tf32f(gelu_f(acc[mt][nt][3])));
        }
}

// ---------------- GEMM-D (R10 version): out = G^T * W1 + b1 + x ----------------
// double-buffered, load-before-compute, 1 sync/panel, 2 CTAs/SM, internal k-perm
#define SMEM_D (4 * 4608 * 4)
__global__ __launch_bounds__(256, 2) void k_gemmD(const float* __restrict__ x,
                                                  const float* __restrict__ W1,
                                                  const float* __restrict__ b1,
                                                  float* __restrict__ out) {
    extern __shared__ unsigned dsm[];
    // layout: A0, A1, B0, B1 (each 4608)
    int col = blockIdx.x;                    // (b,c)
    int b = col >> 5, c = col & 31;
    int tid = threadIdx.x, lane = tid & 31, warp = tid >> 5;
    int wm = warp & 1, wn = warp >> 1, g = lane >> 2, tg = lane & 3;
    float acc[4][4][4] = {};
    uint4 ra[4], rb[4];

    #define GDL(h0) {                                                          \
        _Pragma("unroll") for (int i = 0; i < 4; i++) {                        \
            int idx = tid + i * 256; int kk = idx >> 5, t4 = (idx & 31) * 4;   \
            ra[i] = *(const uint4*)&g_G[(((h0) + kk) * COLS_ + col) * CHK + t4]; } \
        _Pragma("unroll") for (int i = 0; i < 4; i++) {                        \
            int idx = tid + i * 256; int o = idx >> 3, k4 = (idx & 7) * 4;     \
            float4 v = *(const float4*)&W1[o * H_ + (h0) + k4];                \
            rb[i].x = f2tf(v.x); rb[i].y = f2tf(v.y);                          \
            rb[i].z = f2tf(v.z); rb[i].w = f2tf(v.w); } }
    #define GDS(buf) {                                                         \
        unsigned* Ab = dsm + (buf) * 4608;                                     \
        unsigned* Bb = dsm + 2 * 4608 + (buf) * 4608;                          \
        _Pragma("unroll") for (int i = 0; i < 4; i++) {                        \
            int idx = tid + i * 256; int kk = idx >> 5, t4 = (idx & 31) * 4;   \
            int kkp = (kk & 24) | perm8(kk & 7);                               \
            Ab[t4 * 36 + kkp] = ra[i].x; Ab[(t4 + 1) * 36 + kkp] = ra[i].y;    \
            Ab[(t4 + 2) * 36 + kkp] = ra[i].z; Ab[(t4 + 3) * 36 + kkp] = ra[i].w; } \
        _Pragma("unroll") for (int i = 0; i < 4; i++) {                        \
            int idx = tid + i * 256; int o = idx >> 3, k4 = (idx & 7) * 4;     \
            int base = o * 36 + (k4 & ~7) + ((k4 >> 2) & 1);                   \
            Bb[base] = rb[i].x; Bb[base + 2] = rb[i].y;                        \
            Bb[base + 4] = rb[i].z; Bb[base + 6] = rb[i].w; } }

    GDL(0); GDS(0);
    __syncthreads();
    #pragma unroll
    for (int p = 0; p < 4; p++) {
        if (p < 3) GDL((p + 1) * 32);            // load BEFORE compute
        GEMM_PANEL_F2((dsm + (p & 1) * 4608), (dsm + 2 * 4608 + (p & 1) * 4608),
                      acc, wm, wn, g, tg);
        if (p < 3) {
            GDS((p + 1) & 1);
            __syncthreads();
        }
    }
    #pragma unroll
    for (int mt = 0; mt < 4; mt++)
        #pragma unroll
        for (int nt = 0; nt < 4; nt++) {
            int t0 = wm * 64 + mt * 16 + g;
            int o  = wn * 32 + nt * 8 + 2 * tg;
            float2 bias = *(const float2*)&b1[o];
            size_t base0 = ((size_t)b * L_ + c * 128 + t0) * H_ + o;
            size_t base1 = ((size_t)b * L_ + c * 128 + t0 + 8) * H_ + o;
            float2 x0 = *(const float2*)&x[base0];
            float2 x1 = *(const float2*)&x[base1];
            *(float2*)&out[base0] = make_float2(acc[mt][nt][0] + bias.x + x0.x,
                                                acc[mt][nt][1] + bias.y + x0.y);
            *(float2*)&out[base1] = make_float2(acc[mt][nt][2] + bias.x + x1.x,
                                                acc[mt][nt][3] + bias.y + x1.y);
        }
    #undef GDL
    #undef GDS
}

// ---------------- launch ----------------
extern "C" void kernel_launch(void* const* d_in, const int* in_sizes, int n_in,
                              void* d_out, int out_size) {
    const float* x     = (const float*)d_in[0];
    const float* Are   = (const float*)d_in[1];
    const float* Aim   = (const float*)d_in[2];
    const float* Bre   = (const float*)d_in[3];
    const float* Bim   = (const float*)d_in[4];
    const float* Cre   = (const float*)d_in[5];
    const float* Cim   = (const float*)d_in[6];
    const float* Dv    = (const float*)d_in[7];
    const float* logdt = (const float*)d_in[8];
    const float* W1    = (const float*)d_in[9];
    const float* b1    = (const float*)d_in[10];
    float* out = (float*)d_out;

    cudaFuncSetAttribute(k_gemmABC, cudaFuncAttributeMaxDynamicSharedMemorySize, SMEM_ABC);
    cudaFuncSetAttribute(k_gemmD, cudaFuncAttributeMaxDynamicSharedMemorySize, SMEM_D);

    k_powQT<<<H_, 256>>>(Are, Aim, Bre, Bim, Cre, Cim, logdt, Dv);
    k_lnpart<<<dim3(B_, 32), 256>>>(x);
    k_xpose<<<dim3(B_, CHK), 128>>>(x);
    k_gemmABC<<<H_ * 4, 256, SMEM_ABC>>>();
    k_gemmD<<<COLS_, 256, SMEM_D>>>(x, W1, b1, out);
}